// round 1
// baseline (speedup 1.0000x reference)
#include <cuda_runtime.h>
#include <cuda_bf16.h>
#include <math.h>

// Problem constants
#define B_  256
#define T_  256
#define XD_ 512
#define SD_ 512
#define AD_ 512
#define YD_ 6625

// -------- scratch (device globals; no allocation allowed) --------
__device__ float g_sProj[B_ * AD_];     // sProj + (xe_b folded later in epilogue)
__device__ float g_scores[B_ * T_];
__device__ float g_alpha[B_ * T_];
__device__ float g_context[B_ * XD_];
__device__ float g_cc[B_ * (AD_ + XD_)];
__device__ float g_gi[B_ * 3 * SD_];
__device__ float g_gh[B_ * 3 * SD_];
__device__ float g_h[B_ * SD_];

// ======================================================================
// Generic tiled GEMM: C[M,N] = A[M,K] @ Bw[N,K]^T + bias[N]
// A, Bw row-major with K contiguous (TN layout). BM=BN=64, BK=16,
// 256 threads, 4x4 micro-tile per thread. M must be a multiple of 64.
// ======================================================================
template<bool GUARD_N>
__global__ void gemm_tn_bias(const float* __restrict__ A,
                             const float* __restrict__ Bw,
                             const float* __restrict__ bias,
                             float* __restrict__ C,
                             int M, int N, int K)
{
    const int BM = 64, BN = 64, BK = 16;
    __shared__ float As[BK][BM];
    __shared__ float Bs[BK][BN];

    int m0 = blockIdx.y * BM;
    int n0 = blockIdx.x * BN;
    int tid = threadIdx.x;
    int tx = tid & 15;        // 0..15 -> n micro
    int ty = tid >> 4;        // 0..15 -> m micro

    int lrow = tid >> 2;          // 0..63
    int lk4  = (tid & 3) << 2;    // 0,4,8,12

    float acc[4][4] = {};

    for (int k0 = 0; k0 < K; k0 += BK) {
        float4 av;
        {
            const float* p = A + (size_t)(m0 + lrow) * K + k0 + lk4;
            av = *(const float4*)p;
        }
        As[lk4 + 0][lrow] = av.x;
        As[lk4 + 1][lrow] = av.y;
        As[lk4 + 2][lrow] = av.z;
        As[lk4 + 3][lrow] = av.w;

        float4 bv = make_float4(0.f, 0.f, 0.f, 0.f);
        if (!GUARD_N || (n0 + lrow) < N) {
            const float* p = Bw + (size_t)(n0 + lrow) * K + k0 + lk4;
            bv = *(const float4*)p;
        }
        Bs[lk4 + 0][lrow] = bv.x;
        Bs[lk4 + 1][lrow] = bv.y;
        Bs[lk4 + 2][lrow] = bv.z;
        Bs[lk4 + 3][lrow] = bv.w;

        __syncthreads();
        #pragma unroll
        for (int k = 0; k < BK; ++k) {
            float a[4], b[4];
            *(float4*)a = *(const float4*)&As[k][ty * 4];
            *(float4*)b = *(const float4*)&Bs[k][tx * 4];
            #pragma unroll
            for (int i = 0; i < 4; i++)
                #pragma unroll
                for (int j = 0; j < 4; j++)
                    acc[i][j] += a[i] * b[j];
        }
        __syncthreads();
    }

    #pragma unroll
    for (int i = 0; i < 4; i++) {
        int m = m0 + ty * 4 + i;
        #pragma unroll
        for (int j = 0; j < 4; j++) {
            int n = n0 + tx * 4 + j;
            if (GUARD_N && n >= N) continue;
            C[(size_t)m * N + n] = acc[i][j] + bias[n];
        }
    }
}

// ======================================================================
// Big fused GEMM: for rows m = b*T + t over x[65536, 512]:
//   acc[m,n] = x[m,:] . xe_w[n,:]
//   scores[m] += sum_n tanh(acc + xe_b[n] + sProj[b,n]) * we[n]
// Epilogue reduces each thread's 4 columns, then half-warp shfl reduce
// across the 16 n-lanes, then one atomicAdd per (row, n-tile).
// ======================================================================
__global__ void gemm_scores(const float* __restrict__ A,      // x as [B*T, XD]
                            const float* __restrict__ Bw,     // xe_w [AD, XD]
                            const float* __restrict__ xe_b,   // [AD]
                            const float* __restrict__ we)     // we_w [AD]
{
    const int BM = 64, BN = 64, BK = 16;
    const int K = XD_;
    __shared__ float As[BK][BM];
    __shared__ float Bs[BK][BN];

    int m0 = blockIdx.y * BM;
    int n0 = blockIdx.x * BN;
    int tid = threadIdx.x;
    int tx = tid & 15;
    int ty = tid >> 4;

    int lrow = tid >> 2;
    int lk4  = (tid & 3) << 2;

    float acc[4][4] = {};

    for (int k0 = 0; k0 < K; k0 += BK) {
        float4 av = *(const float4*)(A + (size_t)(m0 + lrow) * K + k0 + lk4);
        As[lk4 + 0][lrow] = av.x;
        As[lk4 + 1][lrow] = av.y;
        As[lk4 + 2][lrow] = av.z;
        As[lk4 + 3][lrow] = av.w;

        float4 bv = *(const float4*)(Bw + (size_t)(n0 + lrow) * K + k0 + lk4);
        Bs[lk4 + 0][lrow] = bv.x;
        Bs[lk4 + 1][lrow] = bv.y;
        Bs[lk4 + 2][lrow] = bv.z;
        Bs[lk4 + 3][lrow] = bv.w;

        __syncthreads();
        #pragma unroll
        for (int k = 0; k < BK; ++k) {
            float a[4], b[4];
            *(float4*)a = *(const float4*)&As[k][ty * 4];
            *(float4*)b = *(const float4*)&Bs[k][tx * 4];
            #pragma unroll
            for (int i = 0; i < 4; i++)
                #pragma unroll
                for (int j = 0; j < 4; j++)
                    acc[i][j] += a[i] * b[j];
        }
        __syncthreads();
    }

    // epilogue: tanh + weighted reduce over n
    #pragma unroll
    for (int i = 0; i < 4; i++) {
        int m = m0 + ty * 4 + i;
        int b = m >> 8;   // T_ = 256
        float rowsum = 0.f;
        #pragma unroll
        for (int j = 0; j < 4; j++) {
            int n = n0 + tx * 4 + j;
            float v = tanhf(acc[i][j] + xe_b[n] + g_sProj[b * AD_ + n]) * we[n];
            rowsum += v;
        }
        // reduce across the 16 tx lanes (they occupy one half-warp)
        #pragma unroll
        for (int off = 8; off; off >>= 1)
            rowsum += __shfl_xor_sync(0xffffffffu, rowsum, off);
        if (tx == 0)
            atomicAdd(&g_scores[m], rowsum);
    }
}

__global__ void zero_scores()
{
    int i = blockIdx.x * blockDim.x + threadIdx.x;
    if (i < B_ * T_) g_scores[i] = 0.f;
}

// softmax over T per batch row
__global__ void softmax_kernel()
{
    int b = blockIdx.x;
    int t = threadIdx.x;
    __shared__ float red[T_];
    float v = g_scores[b * T_ + t];
    red[t] = v;
    __syncthreads();
    for (int s = T_ / 2; s; s >>= 1) {
        if (t < s) red[t] = fmaxf(red[t], red[t + s]);
        __syncthreads();
    }
    float mx = red[0];
    __syncthreads();
    float e = expf(v - mx);
    red[t] = e;
    __syncthreads();
    for (int s = T_ / 2; s; s >>= 1) {
        if (t < s) red[t] += red[t + s];
        __syncthreads();
    }
    g_alpha[b * T_ + t] = e / red[0];
}

// context[b,:] = sum_t alpha[b,t] * x[b,t,:]
__global__ void context_kernel(const float* __restrict__ x)
{
    int b = blockIdx.x;
    __shared__ float al[T_];
    al[threadIdx.x] = g_alpha[b * T_ + threadIdx.x];
    __syncthreads();
    const float* xb = x + (size_t)b * T_ * XD_;
    for (int xi = threadIdx.x; xi < XD_; xi += blockDim.x) {
        float acc = 0.f;
        #pragma unroll 8
        for (int t = 0; t < T_; t++)
            acc += al[t] * xb[(size_t)t * XD_ + xi];
        g_context[b * XD_ + xi] = acc;
    }
}

// cc = [emb[yPrev[b]], context[b]]
__global__ void cc_kernel(const float* __restrict__ emb,
                          const int* __restrict__ yPrev)
{
    int b = blockIdx.x;
    int j = threadIdx.x;                     // 0..511
    int y = yPrev[b];
    g_cc[b * 1024 + j]       = emb[(size_t)y * AD_ + j];
    g_cc[b * 1024 + 512 + j] = g_context[b * XD_ + j];
}

// GRU cell elementwise + write h (scratch and optionally output tail)
__global__ void gru_kernel(const float* __restrict__ s,
                           float* __restrict__ h_out)   // may be null
{
    int b = blockIdx.x;
    for (int j = threadIdx.x; j < SD_; j += blockDim.x) {
        float ir = g_gi[b * 3 * SD_ + j];
        float iz = g_gi[b * 3 * SD_ + SD_ + j];
        float in_ = g_gi[b * 3 * SD_ + 2 * SD_ + j];
        float hr = g_gh[b * 3 * SD_ + j];
        float hz = g_gh[b * 3 * SD_ + SD_ + j];
        float hn = g_gh[b * 3 * SD_ + 2 * SD_ + j];
        float r = 1.f / (1.f + expf(-(ir + hr)));
        float z = 1.f / (1.f + expf(-(iz + hz)));
        float n = tanhf(in_ + r * hn);
        float hv = (1.f - z) * n + z * s[b * SD_ + j];
        g_h[b * SD_ + j] = hv;
        if (h_out) h_out[b * SD_ + j] = hv;
    }
}

// ======================================================================
extern "C" void kernel_launch(void* const* d_in, const int* in_sizes, int n_in,
                              void* d_out, int out_size)
{
    const float* x     = (const float*)d_in[0];
    const float* sPrev = (const float*)d_in[1];   // [1,B,SD] -> [B,SD]
    const int*   yPrev = (const int*)  d_in[2];
    const float* xe_w  = (const float*)d_in[3];
    const float* xe_b  = (const float*)d_in[4];
    const float* se_w  = (const float*)d_in[5];
    const float* se_b  = (const float*)d_in[6];
    const float* we_w  = (const float*)d_in[7];
    // d_in[8] = we_b : constant shift, cancels in softmax
    const float* emb   = (const float*)d_in[9];
    const float* w_ih  = (const float*)d_in[10];
    const float* w_hh  = (const float*)d_in[11];
    const float* b_ih  = (const float*)d_in[12];
    const float* b_hh  = (const float*)d_in[13];
    const float* fc_w  = (const float*)d_in[14];
    const float* fc_b  = (const float*)d_in[15];

    float* out = (float*)d_out;
    float* h_out = (out_size >= B_ * YD_ + B_ * SD_) ? out + (size_t)B_ * YD_
                                                     : nullptr;

    // scratch addresses
    float *sProj_p, *gi_p, *gh_p;
    cudaGetSymbolAddress((void**)&sProj_p, g_sProj);
    cudaGetSymbolAddress((void**)&gi_p, g_gi);
    cudaGetSymbolAddress((void**)&gh_p, g_gh);
    float* cc_p;
    cudaGetSymbolAddress((void**)&cc_p, g_cc);
    float* h_p;
    cudaGetSymbolAddress((void**)&h_p, g_h);

    // 0. zero the score accumulator
    zero_scores<<<(B_ * T_ + 1023) / 1024, 1024>>>();

    // 1. sProj = s @ se_w^T + se_b   [256,512]
    gemm_tn_bias<false><<<dim3(AD_ / 64, B_ / 64), 256>>>(
        sPrev, se_w, se_b, sProj_p, B_, AD_, SD_);

    // 2. gh = s @ w_hh^T + b_hh      [256,1536]  (independent)
    gemm_tn_bias<false><<<dim3(3 * SD_ / 64, B_ / 64), 256>>>(
        sPrev, w_hh, b_hh, gh_p, B_, 3 * SD_, SD_);

    // 3. fused attention-score GEMM (needs sProj, scores zeroed)
    gemm_scores<<<dim3(AD_ / 64, (B_ * T_) / 64), 256>>>(x, xe_w, xe_b, we_w);

    // 4. softmax over T
    softmax_kernel<<<B_, T_>>>();

    // 5. context = alpha @ x
    context_kernel<<<B_, 256>>>(x);

    // 6. cc = [emb[yPrev], context]
    cc_kernel<<<B_, 512>>>(emb, yPrev);

    // 7. gi = cc @ w_ih^T + b_ih     [256,1536], K=1024
    gemm_tn_bias<false><<<dim3(3 * SD_ / 64, B_ / 64), 256>>>(
        cc_p, w_ih, b_ih, gi_p, B_, 3 * SD_, XD_ + AD_);

    // 8. GRU elementwise -> h
    gru_kernel<<<B_, 256>>>(sPrev, h_out);

    // 9. logits = h @ fc_w^T + fc_b  [256,6625] -> d_out (guarded N)
    gemm_tn_bias<true><<<dim3((YD_ + 63) / 64, B_ / 64), 256>>>(
        h_p, fc_w, fc_b, out, B_, YD_, SD_);
}

// round 4
// speedup vs baseline: 1.9210x; 1.9210x over previous
#include <cuda_runtime.h>
#include <cuda_bf16.h>
#include <math.h>
#include <stdint.h>

#define B_  256
#define T_  256
#define XD_ 512
#define SD_ 512
#define AD_ 512
#define YD_ 6625

// ---------------- scratch ----------------
__device__ float g_sProj[B_ * AD_];
__device__ float g_scores[B_ * T_];
__device__ float g_alpha[B_ * T_];
__device__ float g_context[B_ * XD_];
__device__ float g_cc[B_ * 1024];
__device__ float g_gi[B_ * 3 * SD_];
__device__ float g_gh[B_ * 3 * SD_];
__device__ float g_h[B_ * SD_];

// split weights (hi/lo bf16), row-major [N][K]
__device__ __nv_bfloat16 g_xe_h[512 * 512],   g_xe_l[512 * 512];
__device__ __nv_bfloat16 g_se_h[512 * 512],   g_se_l[512 * 512];
__device__ __nv_bfloat16 g_hh_h[1536 * 512],  g_hh_l[1536 * 512];
__device__ __nv_bfloat16 g_ih_h[1536 * 1024], g_ih_l[1536 * 1024];
__device__ __nv_bfloat16 g_fc_h[6625 * 512],  g_fc_l[6625 * 512];

// ---------------- helpers ----------------
__device__ __forceinline__ uint32_t smem_u32(const void* p) {
    uint32_t a;
    asm("{ .reg .u64 t; cvta.to.shared.u64 t, %1; cvt.u32.u64 %0, t; }" : "=r"(a) : "l"(p));
    return a;
}
__device__ __forceinline__ void ldmx4(uint32_t addr, uint32_t* r) {
    asm volatile("ldmatrix.sync.aligned.m8n8.x4.shared.b16 {%0,%1,%2,%3}, [%4];"
        : "=r"(r[0]), "=r"(r[1]), "=r"(r[2]), "=r"(r[3]) : "r"(addr));
}
__device__ __forceinline__ void mma_bf16(float* c, const uint32_t* a, uint32_t b0, uint32_t b1) {
    asm volatile("mma.sync.aligned.m16n8k16.row.col.f32.bf16.bf16.f32 "
        "{%0,%1,%2,%3}, {%4,%5,%6,%7}, {%8,%9}, {%0,%1,%2,%3};"
        : "+f"(c[0]), "+f"(c[1]), "+f"(c[2]), "+f"(c[3])
        : "r"(a[0]), "r"(a[1]), "r"(a[2]), "r"(a[3]), "r"(b0), "r"(b1));
}
__device__ __forceinline__ void cpa16(uint32_t dst, const void* src) {
    asm volatile("cp.async.cg.shared.global [%0], [%1], 16;" :: "r"(dst), "l"(src) : "memory");
}
#define CP_COMMIT() asm volatile("cp.async.commit_group;" ::: "memory")
#define CP_WAIT1()  asm volatile("cp.async.wait_group 1;" ::: "memory")
#define CP_WAIT0()  asm volatile("cp.async.wait_group 0;" ::: "memory")

__device__ __forceinline__ float tanh_fast(float x) {
    float xc = fminf(fmaxf(x, -15.f), 15.f);
    float e = exp2f(xc * 2.8853900817779268f);   // e^(2x)
    return __fdividef(e - 1.0f, e + 1.0f);
}

// pack 2 floats -> bf16x2 hi, and residual lo
__device__ __forceinline__ uint32_t pack_hi_lo(float a, float b, uint32_t& lo) {
    __nv_bfloat16 ha = __float2bfloat16(a), hb = __float2bfloat16(b);
    __nv_bfloat16 la = __float2bfloat16(a - __bfloat162float(ha));
    __nv_bfloat16 lb = __float2bfloat16(b - __bfloat162float(hb));
    lo = (uint32_t)*(unsigned short*)&la | ((uint32_t)*(unsigned short*)&lb << 16);
    return (uint32_t)*(unsigned short*)&ha | ((uint32_t)*(unsigned short*)&hb << 16);
}

// ---------------- smem layout ----------------
// padded row stride 80B (32 bf16 + pad) -> conflict-free ldmatrix
#define APAD       80
#define A_TILE_SZ  (128 * APAD)      // 10240
#define W_TILE_SZ  (256 * APAD)      // 20480
#define SM_A       0
#define SM_W       (4 * A_TILE_SZ)                 // 40960
#define SM_TAB     (SM_W + 4 * W_TILE_SZ)          // 122880
#define SMEM_GEMM   SM_TAB
#define SMEM_SCORES (SM_TAB + 2048)

#define A_OFF(buf, hl) (SM_A + ((buf) * 2 + (hl)) * A_TILE_SZ)
#define W_OFF(buf, hl) (SM_W + ((buf) * 2 + (hl)) * W_TILE_SZ)

struct ARegs { float4 v[4]; };

__device__ __forceinline__ void ldgA(ARegs& R, const float* A, int m0, int K, int c, int tid) {
    int row = m0 + (tid >> 1);
    int k0  = c * 32 + (tid & 1) * 16;
    const float4* p = (const float4*)(A + (size_t)row * K + k0);
    R.v[0] = p[0]; R.v[1] = p[1]; R.v[2] = p[2]; R.v[3] = p[3];
}
__device__ __forceinline__ void stsA(const ARegs& R, char* smc, int buf, int tid) {
    uint32_t row = tid >> 1;
    uint32_t cb  = (tid & 1) * 2;
    uint32_t h[8], l[8];
    const float* f = (const float*)R.v;
    #pragma unroll
    for (int i = 0; i < 8; i++) h[i] = pack_hi_lo(f[2 * i], f[2 * i + 1], l[i]);
    uint32_t off = row * APAD + cb * 16;
    *(uint4*)(smc + A_OFF(buf, 0) + off)      = make_uint4(h[0], h[1], h[2], h[3]);
    *(uint4*)(smc + A_OFF(buf, 0) + off + 16) = make_uint4(h[4], h[5], h[6], h[7]);
    *(uint4*)(smc + A_OFF(buf, 1) + off)      = make_uint4(l[0], l[1], l[2], l[3]);
    *(uint4*)(smc + A_OFF(buf, 1) + off + 16) = make_uint4(l[4], l[5], l[6], l[7]);
}

// W tile load: 256 rows x 32 k (hi+lo) = 2048 x 16B, 256 threads -> 8 iters
template<bool GUARD>
__device__ __forceinline__ void loadW(char* smc, uint32_t sm, int buf,
                                      const __nv_bfloat16* Wh, const __nv_bfloat16* Wl,
                                      int nb, int N, int K, int c, int tid) {
    int k0 = c * 32;
    #pragma unroll
    for (int it = 0; it < 8; ++it) {
        int q   = it * 256 + tid;
        int hl  = q >> 10;
        int idx = q & 1023;
        int row = idx >> 2;
        int cc  = idx & 3;
        uint32_t dst = sm + W_OFF(buf, hl) + row * APAD + cc * 16;
        const __nv_bfloat16* src = (hl ? Wl : Wh) + (size_t)(nb + row) * K + k0 + cc * 8;
        if (!GUARD || (nb + row) < N) cpa16(dst, src);
        else *(uint4*)(smc + W_OFF(buf, hl) + row * APAD + cc * 16) = make_uint4(0, 0, 0, 0);
    }
}

// one K-chunk of mma work: warp tile 32x128
__device__ __forceinline__ void compute_chunk(uint32_t sm, int buf, int lane, int wm, int wn,
                                              float (&acc)[2][16][4]) {
    uint32_t aH = sm + A_OFF(buf, 0), aL = sm + A_OFF(buf, 1);
    uint32_t wH = sm + W_OFF(buf, 0), wL = sm + W_OFF(buf, 1);
    #pragma unroll
    for (int ks = 0; ks < 2; ++ks) {
        uint32_t Ah0[4], Ah1[4], Al0[4], Al1[4];
        uint32_t aoff = (uint32_t)(wm + (lane & 15)) * APAD + (uint32_t)(ks * 2 + (lane >> 4)) * 16;
        ldmx4(aH + aoff, Ah0); ldmx4(aH + aoff + 16 * APAD, Ah1);
        ldmx4(aL + aoff, Al0); ldmx4(aL + aoff + 16 * APAD, Al1);
        uint32_t bbase = (uint32_t)(wn + ((lane >> 4) << 3) + (lane & 7)) * APAD +
                         (uint32_t)(ks * 2 + ((lane >> 3) & 1)) * 16;
        #pragma unroll
        for (int g = 0; g < 8; ++g) {
            uint32_t bh[4], bl[4];
            uint32_t boff = bbase + g * 16 * APAD;
            ldmx4(wH + boff, bh); ldmx4(wL + boff, bl);
            #pragma unroll
            for (int h = 0; h < 2; ++h) {
                int nt = g * 2 + h;
                mma_bf16(acc[0][nt], Ah0, bh[2*h], bh[2*h+1]);
                mma_bf16(acc[0][nt], Al0, bh[2*h], bh[2*h+1]);
                mma_bf16(acc[0][nt], Ah0, bl[2*h], bl[2*h+1]);
                mma_bf16(acc[1][nt], Ah1, bh[2*h], bh[2*h+1]);
                mma_bf16(acc[1][nt], Al1, bh[2*h], bh[2*h+1]);
                mma_bf16(acc[1][nt], Ah1, bl[2*h], bl[2*h+1]);
            }
        }
    }
}

// ============ fused attention-scores kernel ============
__global__ void __launch_bounds__(256, 1)
mma_scores(const float* __restrict__ x,
           const float* __restrict__ xe_b,
           const float* __restrict__ we)
{
    extern __shared__ char smc[];
    uint32_t sm = smem_u32(smc);
    int tid = threadIdx.x, lane = tid & 31, wid = tid >> 5;
    int wm = (wid & 3) * 32, wn = (wid >> 2) * 128;
    int m0 = blockIdx.y * 128;
    int nb = blockIdx.x * 256;
    int bidx = blockIdx.y >> 1;

    float* cb_s = (float*)(smc + SM_TAB);
    float* we_s = (float*)(smc + SM_TAB + 1024);
    cb_s[tid] = xe_b[nb + tid] + g_sProj[bidx * 512 + nb + tid];
    we_s[tid] = we[nb + tid];

    float acc[2][16][4];
    #pragma unroll
    for (int a = 0; a < 2; a++)
        #pragma unroll
        for (int b = 0; b < 16; b++)
            #pragma unroll
            for (int cq = 0; cq < 4; cq++) acc[a][b][cq] = 0.f;

    const int NC = 16;
    ARegs R;
    loadW<false>(smc, sm, 0, g_xe_h, g_xe_l, nb, 512, 512, 0, tid); CP_COMMIT();
    ldgA(R, x, m0, 512, 0, tid); stsA(R, smc, 0, tid);
    loadW<false>(smc, sm, 1, g_xe_h, g_xe_l, nb, 512, 512, 1, tid); CP_COMMIT();
    ldgA(R, x, m0, 512, 1, tid);
    CP_WAIT1(); __syncthreads();

    for (int c = 0; c < NC; ++c) {
        compute_chunk(sm, c & 1, lane, wm, wn, acc);
        __syncthreads();
        if (c + 1 < NC) {
            stsA(R, smc, (c + 1) & 1, tid);
            if (c + 2 < NC) {
                loadW<false>(smc, sm, (c + 2) & 1, g_xe_h, g_xe_l, nb, 512, 512, c + 2, tid);
                CP_COMMIT();
                ldgA(R, x, m0, 512, c + 2, tid);
                CP_WAIT1();
            } else CP_WAIT0();
            __syncthreads();
        }
    }

    // epilogue: tanh + weighted row reduction
    #pragma unroll
    for (int mt = 0; mt < 2; ++mt) {
        float s1 = 0.f, s2 = 0.f;
        #pragma unroll
        for (int nt = 0; nt < 16; ++nt) {
            int n = wn + nt * 8 + 2 * (lane & 3);
            float c0 = cb_s[n], c1 = cb_s[n + 1];
            float w0 = we_s[n], w1 = we_s[n + 1];
            s1 += tanh_fast(acc[mt][nt][0] + c0) * w0 + tanh_fast(acc[mt][nt][1] + c1) * w1;
            s2 += tanh_fast(acc[mt][nt][2] + c0) * w0 + tanh_fast(acc[mt][nt][3] + c1) * w1;
        }
        s1 += __shfl_xor_sync(0xffffffffu, s1, 1); s1 += __shfl_xor_sync(0xffffffffu, s1, 2);
        s2 += __shfl_xor_sync(0xffffffffu, s2, 1); s2 += __shfl_xor_sync(0xffffffffu, s2, 2);
        if ((lane & 3) == 0) {
            int r = m0 + wm + mt * 16 + (lane >> 2);
            atomicAdd(&g_scores[r], s1);
            atomicAdd(&g_scores[r + 8], s2);
        }
    }
}

// ============ generic mma GEMM: C = A @ W^T + bias ============
__global__ void __launch_bounds__(256, 1)
mma_gemm(const float* __restrict__ A,
         const __nv_bfloat16* __restrict__ Wh,
         const __nv_bfloat16* __restrict__ Wl,
         const float* __restrict__ bias,
         float* __restrict__ C, int N, int K)
{
    extern __shared__ char smc[];
    uint32_t sm = smem_u32(smc);
    int tid = threadIdx.x, lane = tid & 31, wid = tid >> 5;
    int wm = (wid & 3) * 32, wn = (wid >> 2) * 128;
    int m0 = blockIdx.y * 128;
    int nb = blockIdx.x * 256;

    float acc[2][16][4];
    #pragma unroll
    for (int a = 0; a < 2; a++)
        #pragma unroll
        for (int b = 0; b < 16; b++)
            #pragma unroll
            for (int cq = 0; cq < 4; cq++) acc[a][b][cq] = 0.f;

    const int NC = K >> 5;
    ARegs R;
    loadW<true>(smc, sm, 0, Wh, Wl, nb, N, K, 0, tid); CP_COMMIT();
    ldgA(R, A, m0, K, 0, tid); stsA(R, smc, 0, tid);
    loadW<true>(smc, sm, 1, Wh, Wl, nb, N, K, 1, tid); CP_COMMIT();
    ldgA(R, A, m0, K, 1, tid);
    CP_WAIT1(); __syncthreads();

    for (int c = 0; c < NC; ++c) {
        compute_chunk(sm, c & 1, lane, wm, wn, acc);
        __syncthreads();
        if (c + 1 < NC) {
            stsA(R, smc, (c + 1) & 1, tid);
            if (c + 2 < NC) {
                loadW<true>(smc, sm, (c + 2) & 1, Wh, Wl, nb, N, K, c + 2, tid);
                CP_COMMIT();
                ldgA(R, A, m0, K, c + 2, tid);
                CP_WAIT1();
            } else CP_WAIT0();
            __syncthreads();
        }
    }

    #pragma unroll
    for (int mt = 0; mt < 2; ++mt) {
        int r1 = m0 + wm + mt * 16 + (lane >> 2);
        int r2 = r1 + 8;
        #pragma unroll
        for (int nt = 0; nt < 16; ++nt) {
            int n = nb + wn + nt * 8 + 2 * (lane & 3);
            if (n < N) {
                float b0 = bias[n];
                C[(size_t)r1 * N + n] = acc[mt][nt][0] + b0;
                C[(size_t)r2 * N + n] = acc[mt][nt][2] + b0;
                if (n + 1 < N) {
                    float b1 = bias[n + 1];
                    C[(size_t)r1 * N + n + 1] = acc[mt][nt][1] + b1;
                    C[(size_t)r2 * N + n + 1] = acc[mt][nt][3] + b1;
                }
            }
        }
    }
}

// ---------------- small kernels ----------------
__global__ void split_w(const float* __restrict__ w,
                        __nv_bfloat16* __restrict__ hi,
                        __nv_bfloat16* __restrict__ lo, int n)
{
    int i = (blockIdx.x * blockDim.x + threadIdx.x) * 4;
    if (i >= n) return;
    float4 v = *(const float4*)(w + i);
    float f[4] = {v.x, v.y, v.z, v.w};
    unsigned short hb[4], lb[4];
    #pragma unroll
    for (int j = 0; j < 4; j++) {
        __nv_bfloat16 h = __float2bfloat16(f[j]);
        __nv_bfloat16 l = __float2bfloat16(f[j] - __bfloat162float(h));
        hb[j] = *(unsigned short*)&h; lb[j] = *(unsigned short*)&l;
    }
    *(uint2*)(hi + i) = make_uint2((uint32_t)hb[0] | ((uint32_t)hb[1] << 16),
                                   (uint32_t)hb[2] | ((uint32_t)hb[3] << 16));
    *(uint2*)(lo + i) = make_uint2((uint32_t)lb[0] | ((uint32_t)lb[1] << 16),
                                   (uint32_t)lb[2] | ((uint32_t)lb[3] << 16));
}

__global__ void zero_scores() {
    int i = blockIdx.x * blockDim.x + threadIdx.x;
    if (i < B_ * T_) g_scores[i] = 0.f;
}

__global__ void softmax_kernel() {
    int b = blockIdx.x, t = threadIdx.x;
    __shared__ float red[T_];
    float v = g_scores[b * T_ + t];
    red[t] = v; __syncthreads();
    for (int s = T_ / 2; s; s >>= 1) { if (t < s) red[t] = fmaxf(red[t], red[t + s]); __syncthreads(); }
    float mx = red[0]; __syncthreads();
    float e = expf(v - mx);
    red[t] = e; __syncthreads();
    for (int s = T_ / 2; s; s >>= 1) { if (t < s) red[t] += red[t + s]; __syncthreads(); }
    g_alpha[b * T_ + t] = e / red[0];
}

__global__ void context_kernel(const float* __restrict__ x) {
    int b = blockIdx.x;
    __shared__ float al[T_];
    al[threadIdx.x] = g_alpha[b * T_ + threadIdx.x];
    al[threadIdx.x + 128] = g_alpha[b * T_ + threadIdx.x + 128];
    __syncthreads();
    const float4* xb = (const float4*)(x + (size_t)b * T_ * XD_);
    int col = threadIdx.x;
    float4 acc = make_float4(0.f, 0.f, 0.f, 0.f);
    #pragma unroll 4
    for (int t = 0; t < T_; t++) {
        float a = al[t];
        float4 v = xb[t * (XD_ / 4) + col];
        acc.x += a * v.x; acc.y += a * v.y; acc.z += a * v.z; acc.w += a * v.w;
    }
    *(float4*)(g_context + b * XD_ + col * 4) = acc;
}

__global__ void cc_kernel(const float* __restrict__ emb, const int* __restrict__ yPrev) {
    int b = blockIdx.x, j = threadIdx.x;
    int y = yPrev[b];
    g_cc[b * 1024 + j]       = emb[(size_t)y * AD_ + j];
    g_cc[b * 1024 + 512 + j] = g_context[b * XD_ + j];
}

__global__ void gru_kernel(const float* __restrict__ s, float* __restrict__ h_out) {
    int b = blockIdx.x;
    for (int j = threadIdx.x; j < SD_; j += blockDim.x) {
        float ir = g_gi[b * 3 * SD_ + j];
        float iz = g_gi[b * 3 * SD_ + SD_ + j];
        float in_ = g_gi[b * 3 * SD_ + 2 * SD_ + j];
        float hr = g_gh[b * 3 * SD_ + j];
        float hz = g_gh[b * 3 * SD_ + SD_ + j];
        float hn = g_gh[b * 3 * SD_ + 2 * SD_ + j];
        float r = 1.f / (1.f + expf(-(ir + hr)));
        float z = 1.f / (1.f + expf(-(iz + hz)));
        float n = tanhf(in_ + r * hn);
        float hv = (1.f - z) * n + z * s[b * SD_ + j];
        g_h[b * SD_ + j] = hv;
        if (h_out) h_out[b * SD_ + j] = hv;
    }
}

// ======================================================================
extern "C" void kernel_launch(void* const* d_in, const int* in_sizes, int n_in,
                              void* d_out, int out_size)
{
    const float* x     = (const float*)d_in[0];
    const float* sPrev = (const float*)d_in[1];
    const int*   yPrev = (const int*)  d_in[2];
    const float* xe_w  = (const float*)d_in[3];
    const float* xe_b  = (const float*)d_in[4];
    const float* se_w  = (const float*)d_in[5];
    const float* se_b  = (const float*)d_in[6];
    const float* we_w  = (const float*)d_in[7];
    const float* emb   = (const float*)d_in[9];
    const float* w_ih  = (const float*)d_in[10];
    const float* w_hh  = (const float*)d_in[11];
    const float* b_ih  = (const float*)d_in[12];
    const float* b_hh  = (const float*)d_in[13];
    const float* fc_w  = (const float*)d_in[14];
    const float* fc_b  = (const float*)d_in[15];

    float* out = (float*)d_out;
    float* h_out = (out_size >= B_ * YD_ + B_ * SD_) ? out + (size_t)B_ * YD_ : nullptr;

    float *sProj_p, *gi_p, *gh_p, *cc_p, *h_p;
    cudaGetSymbolAddress((void**)&sProj_p, g_sProj);
    cudaGetSymbolAddress((void**)&gi_p, g_gi);
    cudaGetSymbolAddress((void**)&gh_p, g_gh);
    cudaGetSymbolAddress((void**)&cc_p, g_cc);
    cudaGetSymbolAddress((void**)&h_p, g_h);
    __nv_bfloat16 *xe_h, *xe_l, *se_h, *se_l, *hh_h, *hh_l, *ih_h, *ih_l, *fc_h, *fc_l;
    cudaGetSymbolAddress((void**)&xe_h, g_xe_h); cudaGetSymbolAddress((void**)&xe_l, g_xe_l);
    cudaGetSymbolAddress((void**)&se_h, g_se_h); cudaGetSymbolAddress((void**)&se_l, g_se_l);
    cudaGetSymbolAddress((void**)&hh_h, g_hh_h); cudaGetSymbolAddress((void**)&hh_l, g_hh_l);
    cudaGetSymbolAddress((void**)&ih_h, g_ih_h); cudaGetSymbolAddress((void**)&ih_l, g_ih_l);
    cudaGetSymbolAddress((void**)&fc_h, g_fc_h); cudaGetSymbolAddress((void**)&fc_l, g_fc_l);

    static bool inited = false;
    if (!inited) {
        cudaFuncSetAttribute(mma_scores, cudaFuncAttributeMaxDynamicSharedMemorySize, SMEM_SCORES);
        cudaFuncSetAttribute(mma_gemm,   cudaFuncAttributeMaxDynamicSharedMemorySize, SMEM_GEMM);
        inited = true;
    }

    // weight splits (ceil-div grids! 6625*512/1024 truncated before -> R3 bug)
    #define CEIL_DIV(a, b) (((a) + (b) - 1) / (b))
    split_w<<<CEIL_DIV(512 * 512, 1024), 256>>>(xe_w, xe_h, xe_l, 512 * 512);
    split_w<<<CEIL_DIV(512 * 512, 1024), 256>>>(se_w, se_h, se_l, 512 * 512);
    split_w<<<CEIL_DIV(1536 * 512, 1024), 256>>>(w_hh, hh_h, hh_l, 1536 * 512);
    split_w<<<CEIL_DIV(1536 * 1024, 1024), 256>>>(w_ih, ih_h, ih_l, 1536 * 1024);
    split_w<<<CEIL_DIV(6625 * 512, 1024), 256>>>(fc_w, fc_h, fc_l, 6625 * 512);

    zero_scores<<<(B_ * T_ + 1023) / 1024, 1024>>>();

    // sProj = s @ se_w^T + se_b   [256,512]
    mma_gemm<<<dim3(2, 2), 256, SMEM_GEMM>>>(sPrev, se_h, se_l, se_b, sProj_p, 512, 512);
    // gh = s @ w_hh^T + b_hh      [256,1536]
    mma_gemm<<<dim3(6, 2), 256, SMEM_GEMM>>>(sPrev, hh_h, hh_l, b_hh, gh_p, 1536, 512);

    // attention scores (fused epilogue)
    mma_scores<<<dim3(2, 512), 256, SMEM_SCORES>>>(x, xe_b, we_w);

    softmax_kernel<<<B_, T_>>>();
    context_kernel<<<B_, 128>>>(x);
    cc_kernel<<<B_, 512>>>(emb, yPrev);

    // gi = cc @ w_ih^T + b_ih     [256,1536], K=1024
    mma_gemm<<<dim3(6, 2), 256, SMEM_GEMM>>>(cc_p, ih_h, ih_l, b_ih, gi_p, 1536, 1024);

    gru_kernel<<<B_, 256>>>(sPrev, h_out);

    // logits = h @ fc_w^T + fc_b  [256,6625]
    mma_gemm<<<dim3(26, 2), 256, SMEM_GEMM>>>(h_p, fc_h, fc_l, fc_b, out, 6625, 512);
}

// round 5
// speedup vs baseline: 2.0771x; 1.0813x over previous
#include <cuda_runtime.h>
#include <cuda_bf16.h>
#include <math.h>
#include <stdint.h>

#define B_  256
#define T_  256
#define XD_ 512
#define SD_ 512
#define AD_ 512
#define YD_ 6625

// ---------------- scratch ----------------
__device__ float g_sProj[B_ * AD_];
__device__ float g_spart[2 * B_ * T_];      // per-nb score partials
__device__ float g_gi[B_ * 3 * SD_];
__device__ float g_gh[B_ * 3 * SD_];

// split activations (hi/lo bf16)
__device__ __nv_bfloat16 g_xh[B_ * T_ * XD_], g_xl[B_ * T_ * XD_];
__device__ __nv_bfloat16 g_sh[B_ * SD_],      g_sl[B_ * SD_];
__device__ __nv_bfloat16 g_cch[B_ * 1024],    g_ccl[B_ * 1024];
__device__ __nv_bfloat16 g_hh2[B_ * SD_],     g_hl2[B_ * SD_];

// split weights (hi/lo bf16), row-major [N][K]
__device__ __nv_bfloat16 g_xe_h[512 * 512],   g_xe_l[512 * 512];
__device__ __nv_bfloat16 g_se_h[512 * 512],   g_se_l[512 * 512];
__device__ __nv_bfloat16 g_hh_h[1536 * 512],  g_hh_l[1536 * 512];
__device__ __nv_bfloat16 g_ih_h[1536 * 1024], g_ih_l[1536 * 1024];
__device__ __nv_bfloat16 g_fc_h[6625 * 512],  g_fc_l[6625 * 512];

// ---------------- helpers ----------------
__device__ __forceinline__ uint32_t smem_u32(const void* p) {
    uint32_t a;
    asm("{ .reg .u64 t; cvta.to.shared.u64 t, %1; cvt.u32.u64 %0, t; }" : "=r"(a) : "l"(p));
    return a;
}
__device__ __forceinline__ void ldmx4(uint32_t addr, uint32_t* r) {
    asm volatile("ldmatrix.sync.aligned.m8n8.x4.shared.b16 {%0,%1,%2,%3}, [%4];"
        : "=r"(r[0]), "=r"(r[1]), "=r"(r[2]), "=r"(r[3]) : "r"(addr));
}
__device__ __forceinline__ void mma_bf16(float* c, const uint32_t* a, uint32_t b0, uint32_t b1) {
    asm volatile("mma.sync.aligned.m16n8k16.row.col.f32.bf16.bf16.f32 "
        "{%0,%1,%2,%3}, {%4,%5,%6,%7}, {%8,%9}, {%0,%1,%2,%3};"
        : "+f"(c[0]), "+f"(c[1]), "+f"(c[2]), "+f"(c[3])
        : "r"(a[0]), "r"(a[1]), "r"(a[2]), "r"(a[3]), "r"(b0), "r"(b1));
}
__device__ __forceinline__ void cpa16(uint32_t dst, const void* src) {
    asm volatile("cp.async.cg.shared.global [%0], [%1], 16;" :: "r"(dst), "l"(src) : "memory");
}
#define CP_COMMIT() asm volatile("cp.async.commit_group;" ::: "memory")
#define CP_WAIT1()  asm volatile("cp.async.wait_group 1;" ::: "memory")
#define CP_WAIT0()  asm volatile("cp.async.wait_group 0;" ::: "memory")

__device__ __forceinline__ float tanh_fast(float x) {
    float xc = fminf(fmaxf(x, -15.f), 15.f);
    float e = exp2f(xc * 2.8853900817779268f);
    return __fdividef(e - 1.0f, e + 1.0f);
}
__device__ __forceinline__ uint32_t pack_hi_lo(float a, float b, uint32_t& lo) {
    __nv_bfloat16 ha = __float2bfloat16(a), hb = __float2bfloat16(b);
    __nv_bfloat16 la = __float2bfloat16(a - __bfloat162float(ha));
    __nv_bfloat16 lb = __float2bfloat16(b - __bfloat162float(hb));
    lo = (uint32_t)*(unsigned short*)&la | ((uint32_t)*(unsigned short*)&lb << 16);
    return (uint32_t)*(unsigned short*)&ha | ((uint32_t)*(unsigned short*)&hb << 16);
}

// ---------------- smem layout ----------------
#define APAD     80
#define A_HL     (128 * APAD)          // 10240 (one hi or lo plane of A)
#define A_STG    (2 * A_HL)            // 20480
#define W_HL     (256 * APAD)          // 20480
#define W_STG    (2 * W_HL)            // 40960
#define STG_SZ   (A_STG + W_STG)       // 61440
#define SM_STAGE(s) ((s) * STG_SZ)
#define SM_TAB   (3 * STG_SZ)          // 184320
#define SMEM_GEMM   SM_TAB
#define SMEM_SCORES (SM_TAB + 4096)

// ---------------- stage loader ----------------
template<bool GUARD>
__device__ __forceinline__ void load_stage(char* smc, uint32_t sm, int stage,
        const __nv_bfloat16* Ah, const __nv_bfloat16* Al,
        const __nv_bfloat16* Wh, const __nv_bfloat16* Wl,
        int m0, int nb, int N, int K, int c, int tid)
{
    uint32_t base = sm + SM_STAGE(stage);
    int k0 = c * 32;
    #pragma unroll
    for (int it = 0; it < 4; ++it) {          // A: 128 rows x 64B x 2
        int idx = it * 256 + tid;
        int hl = idx >> 9, rem = idx & 511, r = rem >> 2, c4 = rem & 3;
        const __nv_bfloat16* src = (hl ? Al : Ah) + (size_t)(m0 + r) * K + k0 + c4 * 8;
        cpa16(base + hl * A_HL + r * APAD + c4 * 16, src);
    }
    #pragma unroll
    for (int it = 0; it < 8; ++it) {          // W: 256 rows x 64B x 2
        int idx = it * 256 + tid;
        int hl = idx >> 10, rem = idx & 1023, r = rem >> 2, c4 = rem & 3;
        uint32_t dst = base + A_STG + hl * W_HL + r * APAD + c4 * 16;
        if (!GUARD || (nb + r) < N)
            cpa16(dst, (hl ? Wl : Wh) + (size_t)(nb + r) * K + k0 + c4 * 8);
        else
            *(uint4*)(smc + (dst - sm)) = make_uint4(0, 0, 0, 0);
    }
}

// ---------------- K-chunk compute: warp 64x64 ----------------
__device__ __forceinline__ void compute_chunk3(uint32_t sm, int stage, int lane,
                                               int wm, int wn, float (&acc)[4][8][4])
{
    uint32_t aB = sm + SM_STAGE(stage);
    uint32_t wB = aB + A_STG;
    #pragma unroll
    for (int ks = 0; ks < 2; ++ks) {
        uint32_t Ah[4][4], Al[4][4];
        #pragma unroll
        for (int mt = 0; mt < 4; ++mt) {
            uint32_t aoff = (uint32_t)(wm + mt * 16 + (lane & 15)) * APAD
                          + (uint32_t)(ks * 2 + (lane >> 4)) * 16;
            ldmx4(aB + aoff, Ah[mt]);
            ldmx4(aB + A_HL + aoff, Al[mt]);
        }
        #pragma unroll
        for (int g = 0; g < 4; ++g) {
            uint32_t bh[4], bl[4];
            uint32_t boff = (uint32_t)(wn + g * 16 + ((lane >> 4) << 3) + (lane & 7)) * APAD
                          + (uint32_t)(ks * 2 + ((lane >> 3) & 1)) * 16;
            ldmx4(wB + boff, bh);
            ldmx4(wB + W_HL + boff, bl);
            #pragma unroll
            for (int mt = 0; mt < 4; ++mt) {
                #pragma unroll
                for (int h = 0; h < 2; ++h) {
                    float* c = acc[mt][g * 2 + h];
                    mma_bf16(c, Ah[mt], bh[2 * h], bh[2 * h + 1]);
                    mma_bf16(c, Al[mt], bh[2 * h], bh[2 * h + 1]);
                    mma_bf16(c, Ah[mt], bl[2 * h], bl[2 * h + 1]);
                }
            }
        }
    }
}

// ---------------- main K-loop (shared) ----------------
template<bool GUARD>
__device__ __forceinline__ void run_mainloop(char* smc, uint32_t sm,
        const __nv_bfloat16* Ah, const __nv_bfloat16* Al,
        const __nv_bfloat16* Wh, const __nv_bfloat16* Wl,
        int m0, int nb, int N, int K, int tid, int lane, int wm, int wn,
        float (&acc)[4][8][4])
{
    int NC = K >> 5;
    load_stage<GUARD>(smc, sm, 0, Ah, Al, Wh, Wl, m0, nb, N, K, 0, tid); CP_COMMIT();
    load_stage<GUARD>(smc, sm, 1, Ah, Al, Wh, Wl, m0, nb, N, K, 1, tid); CP_COMMIT();
    for (int c = 0; c < NC; ++c) {
        if (c < NC - 1) CP_WAIT1(); else CP_WAIT0();
        __syncthreads();
        if (c + 2 < NC) {
            load_stage<GUARD>(smc, sm, (c + 2) % 3, Ah, Al, Wh, Wl, m0, nb, N, K, c + 2, tid);
            CP_COMMIT();
        }
        compute_chunk3(sm, c % 3, lane, wm, wn, acc);
    }
}

// ============ generic GEMM: C = A @ W^T + bias ============
template<bool GUARD>
__global__ void __launch_bounds__(256, 1)
mma3_gemm(const __nv_bfloat16* __restrict__ Ah, const __nv_bfloat16* __restrict__ Al,
          const __nv_bfloat16* __restrict__ Wh, const __nv_bfloat16* __restrict__ Wl,
          const float* __restrict__ bias, float* __restrict__ C, int N, int K)
{
    extern __shared__ char smc[];
    uint32_t sm = smem_u32(smc);
    int tid = threadIdx.x, lane = tid & 31, wid = tid >> 5;
    int wm = (wid >> 2) * 64, wn = (wid & 3) * 64;
    int m0 = blockIdx.y * 128, nb = blockIdx.x * 256;

    float acc[4][8][4] = {};
    run_mainloop<GUARD>(smc, sm, Ah, Al, Wh, Wl, m0, nb, N, K, tid, lane, wm, wn, acc);

    #pragma unroll
    for (int mt = 0; mt < 4; ++mt) {
        int r1 = m0 + wm + mt * 16 + (lane >> 2), r2 = r1 + 8;
        #pragma unroll
        for (int nt = 0; nt < 8; ++nt) {
            int n = nb + wn + nt * 8 + 2 * (lane & 3);
            if (!GUARD || n < N) {
                float b0 = bias[n];
                C[(size_t)r1 * N + n] = acc[mt][nt][0] + b0;
                C[(size_t)r2 * N + n] = acc[mt][nt][2] + b0;
                if (!GUARD || n + 1 < N) {
                    float b1 = bias[n + 1];
                    C[(size_t)r1 * N + n + 1] = acc[mt][nt][1] + b1;
                    C[(size_t)r2 * N + n + 1] = acc[mt][nt][3] + b1;
                }
            }
        }
    }
}

// ============ fused attention-scores GEMM ============
__global__ void __launch_bounds__(256, 1)
mma3_scores(const float* __restrict__ xe_b, const float* __restrict__ we)
{
    extern __shared__ char smc[];
    uint32_t sm = smem_u32(smc);
    int tid = threadIdx.x, lane = tid & 31, wid = tid >> 5;
    int wm = (wid >> 2) * 64, wn = (wid & 3) * 64;
    int wx = wid & 3;
    int m0 = blockIdx.y * 128, nb = blockIdx.x * 256;
    int bidx = blockIdx.y >> 1;

    float* cb_s = (float*)(smc + SM_TAB);
    float* we_s = cb_s + 256;
    float* part = we_s + 256;   // [4][128]
    cb_s[tid] = xe_b[nb + tid] + g_sProj[bidx * 512 + nb + tid];
    we_s[tid] = we[nb + tid];

    float acc[4][8][4] = {};
    run_mainloop<false>(smc, sm, g_xh, g_xl, g_xe_h, g_xe_l,
                        m0, nb, 512, 512, tid, lane, wm, wn, acc);

    #pragma unroll
    for (int mt = 0; mt < 4; ++mt) {
        float s1 = 0.f, s2 = 0.f;
        #pragma unroll
        for (int nt = 0; nt < 8; ++nt) {
            int n = wn + nt * 8 + 2 * (lane & 3);
            float c0 = cb_s[n], c1 = cb_s[n + 1];
            float w0 = we_s[n], w1 = we_s[n + 1];
            s1 += tanh_fast(acc[mt][nt][0] + c0) * w0 + tanh_fast(acc[mt][nt][1] + c1) * w1;
            s2 += tanh_fast(acc[mt][nt][2] + c0) * w0 + tanh_fast(acc[mt][nt][3] + c1) * w1;
        }
        s1 += __shfl_xor_sync(0xffffffffu, s1, 1); s1 += __shfl_xor_sync(0xffffffffu, s1, 2);
        s2 += __shfl_xor_sync(0xffffffffu, s2, 1); s2 += __shfl_xor_sync(0xffffffffu, s2, 2);
        if ((lane & 3) == 0) {
            int rl = wm + mt * 16 + (lane >> 2);
            part[wx * 128 + rl]     = s1;
            part[wx * 128 + rl + 8] = s2;
        }
    }
    __syncthreads();
    if (tid < 128)
        g_spart[blockIdx.x * (B_ * T_) + m0 + tid] =
            part[tid] + part[128 + tid] + part[256 + tid] + part[384 + tid];
}

// ---------------- splits ----------------
__device__ __forceinline__ void split4_at(const float* __restrict__ w,
                                          __nv_bfloat16* __restrict__ hi,
                                          __nv_bfloat16* __restrict__ lo, int i)
{
    float4 v = *(const float4*)(w + i);
    float f[4] = {v.x, v.y, v.z, v.w};
    unsigned short hb[4], lb[4];
    #pragma unroll
    for (int j = 0; j < 4; j++) {
        __nv_bfloat16 h = __float2bfloat16(f[j]);
        __nv_bfloat16 l = __float2bfloat16(f[j] - __bfloat162float(h));
        hb[j] = *(unsigned short*)&h; lb[j] = *(unsigned short*)&l;
    }
    *(uint2*)(hi + i) = make_uint2((uint32_t)hb[0] | ((uint32_t)hb[1] << 16),
                                   (uint32_t)hb[2] | ((uint32_t)hb[3] << 16));
    *(uint2*)(lo + i) = make_uint2((uint32_t)lb[0] | ((uint32_t)lb[1] << 16),
                                   (uint32_t)lb[2] | ((uint32_t)lb[3] << 16));
}

__global__ void split4(const float* __restrict__ w,
                       __nv_bfloat16* __restrict__ hi,
                       __nv_bfloat16* __restrict__ lo, int nquads)
{
    int q = blockIdx.x * blockDim.x + threadIdx.x;
    if (q < nquads) split4_at(w, hi, lo, q * 4);
}

// all 5 weight matrices in one launch
#define Q_XE 65536
#define Q_SE 65536
#define Q_HH 196608
#define Q_IH 393216
#define Q_FC 848000
#define Q_TOT (Q_XE + Q_SE + Q_HH + Q_IH + Q_FC)
__global__ void split_weights(const float* xe, const float* se, const float* hh,
                              const float* ih, const float* fc)
{
    int q = blockIdx.x * blockDim.x + threadIdx.x;
    if (q >= Q_TOT) return;
    if (q < Q_XE)                        { split4_at(xe, g_xe_h, g_xe_l, q * 4); return; }
    q -= Q_XE;
    if (q < Q_SE)                        { split4_at(se, g_se_h, g_se_l, q * 4); return; }
    q -= Q_SE;
    if (q < Q_HH)                        { split4_at(hh, g_hh_h, g_hh_l, q * 4); return; }
    q -= Q_HH;
    if (q < Q_IH)                        { split4_at(ih, g_ih_h, g_ih_l, q * 4); return; }
    q -= Q_IH;
    split4_at(fc, g_fc_h, g_fc_l, q * 4);
}

// ---------------- fused softmax + context + cc ----------------
__global__ void softmax_ctx_cc(const float* __restrict__ x,
                               const float* __restrict__ emb,
                               const int* __restrict__ yPrev)
{
    int b = blockIdx.x, t = threadIdx.x;
    __shared__ float al[T_];
    __shared__ float red[T_];
    float v = g_spart[b * T_ + t] + g_spart[B_ * T_ + b * T_ + t];
    red[t] = v; __syncthreads();
    for (int s = T_ / 2; s; s >>= 1) { if (t < s) red[t] = fmaxf(red[t], red[t + s]); __syncthreads(); }
    float mx = red[0]; __syncthreads();
    float e = expf(v - mx);
    red[t] = e; __syncthreads();
    for (int s = T_ / 2; s; s >>= 1) { if (t < s) red[t] += red[t + s]; __syncthreads(); }
    al[t] = e / red[0];
    __syncthreads();

    const float* xb = x + (size_t)b * T_ * XD_;
    float c0 = 0.f, c1 = 0.f;
    #pragma unroll 4
    for (int tt = 0; tt < T_; ++tt) {
        float a = al[tt];
        float2 xv = *(const float2*)(xb + (size_t)tt * XD_ + 2 * t);
        c0 += a * xv.x; c1 += a * xv.y;
    }
    uint32_t lo, hi;
    hi = pack_hi_lo(c0, c1, lo);
    ((uint32_t*)(g_cch + b * 1024 + 512))[t] = hi;
    ((uint32_t*)(g_ccl + b * 1024 + 512))[t] = lo;

    int y = yPrev[b];
    float2 ev = *(const float2*)(emb + (size_t)y * AD_ + 2 * t);
    hi = pack_hi_lo(ev.x, ev.y, lo);
    ((uint32_t*)(g_cch + b * 1024))[t] = hi;
    ((uint32_t*)(g_ccl + b * 1024))[t] = lo;
}

// ---------------- GRU elementwise ----------------
__global__ void gru_kernel(const float* __restrict__ s, float* __restrict__ h_out)
{
    int b = blockIdx.x;
    for (int j = threadIdx.x; j < SD_; j += blockDim.x) {
        float ir = g_gi[b * 3 * SD_ + j];
        float iz = g_gi[b * 3 * SD_ + SD_ + j];
        float in_ = g_gi[b * 3 * SD_ + 2 * SD_ + j];
        float hr = g_gh[b * 3 * SD_ + j];
        float hz = g_gh[b * 3 * SD_ + SD_ + j];
        float hn = g_gh[b * 3 * SD_ + 2 * SD_ + j];
        float r = 1.f / (1.f + expf(-(ir + hr)));
        float z = 1.f / (1.f + expf(-(iz + hz)));
        float n = tanhf(in_ + r * hn);
        float hv = (1.f - z) * n + z * s[b * SD_ + j];
        __nv_bfloat16 hb = __float2bfloat16(hv);
        g_hh2[b * SD_ + j] = hb;
        g_hl2[b * SD_ + j] = __float2bfloat16(hv - __bfloat162float(hb));
        if (h_out) h_out[b * SD_ + j] = hv;
    }
}

// ======================================================================
extern "C" void kernel_launch(void* const* d_in, const int* in_sizes, int n_in,
                              void* d_out, int out_size)
{
    const float* x     = (const float*)d_in[0];
    const float* sPrev = (const float*)d_in[1];
    const int*   yPrev = (const int*)  d_in[2];
    const float* xe_w  = (const float*)d_in[3];
    const float* xe_b  = (const float*)d_in[4];
    const float* se_w  = (const float*)d_in[5];
    const float* se_b  = (const float*)d_in[6];
    const float* we_w  = (const float*)d_in[7];
    const float* emb   = (const float*)d_in[9];
    const float* w_ih  = (const float*)d_in[10];
    const float* w_hh  = (const float*)d_in[11];
    const float* b_ih  = (const float*)d_in[12];
    const float* b_hh  = (const float*)d_in[13];
    const float* fc_w  = (const float*)d_in[14];
    const float* fc_b  = (const float*)d_in[15];

    float* out = (float*)d_out;
    float* h_out = (out_size >= B_ * YD_ + B_ * SD_) ? out + (size_t)B_ * YD_ : nullptr;

    float *sProj_p, *gi_p, *gh_p;
    cudaGetSymbolAddress((void**)&sProj_p, g_sProj);
    cudaGetSymbolAddress((void**)&gi_p, g_gi);
    cudaGetSymbolAddress((void**)&gh_p, g_gh);
    __nv_bfloat16 *xh, *xl, *sh, *sl, *cch, *ccl, *hh2, *hl2;
    cudaGetSymbolAddress((void**)&xh, g_xh);   cudaGetSymbolAddress((void**)&xl, g_xl);
    cudaGetSymbolAddress((void**)&sh, g_sh);   cudaGetSymbolAddress((void**)&sl, g_sl);
    cudaGetSymbolAddress((void**)&cch, g_cch); cudaGetSymbolAddress((void**)&ccl, g_ccl);
    cudaGetSymbolAddress((void**)&hh2, g_hh2); cudaGetSymbolAddress((void**)&hl2, g_hl2);
    __nv_bfloat16 *se_h, *se_l, *hh_h, *hh_l, *ih_h, *ih_l, *fc_h, *fc_l;
    cudaGetSymbolAddress((void**)&se_h, g_se_h); cudaGetSymbolAddress((void**)&se_l, g_se_l);
    cudaGetSymbolAddress((void**)&hh_h, g_hh_h); cudaGetSymbolAddress((void**)&hh_l, g_hh_l);
    cudaGetSymbolAddress((void**)&ih_h, g_ih_h); cudaGetSymbolAddress((void**)&ih_l, g_ih_l);
    cudaGetSymbolAddress((void**)&fc_h, g_fc_h); cudaGetSymbolAddress((void**)&fc_l, g_fc_l);

    static bool inited = false;
    if (!inited) {
        cudaFuncSetAttribute(mma3_scores,      cudaFuncAttributeMaxDynamicSharedMemorySize, SMEM_SCORES);
        cudaFuncSetAttribute(mma3_gemm<false>, cudaFuncAttributeMaxDynamicSharedMemorySize, SMEM_GEMM);
        cudaFuncSetAttribute(mma3_gemm<true>,  cudaFuncAttributeMaxDynamicSharedMemorySize, SMEM_GEMM);
        inited = true;
    }

    #define CEIL_DIV(a, b) (((a) + (b) - 1) / (b))

    // 1. all weight splits (one launch)
    split_weights<<<CEIL_DIV(Q_TOT, 256), 256>>>(xe_w, se_w, w_hh, w_ih, fc_w);
    // 2. x split
    split4<<<CEIL_DIV(B_ * T_ * XD_ / 4, 256), 256>>>(x, xh, xl, B_ * T_ * XD_ / 4);
    // 3. sPrev split
    split4<<<CEIL_DIV(B_ * SD_ / 4, 256), 256>>>(sPrev, sh, sl, B_ * SD_ / 4);
    // 4. sProj = s @ se_w^T + se_b   [256,512]
    mma3_gemm<false><<<dim3(2, 2), 256, SMEM_GEMM>>>(sh, sl, se_h, se_l, se_b, sProj_p, 512, 512);
    // 5. gh = s @ w_hh^T + b_hh      [256,1536]
    mma3_gemm<false><<<dim3(6, 2), 256, SMEM_GEMM>>>(sh, sl, hh_h, hh_l, b_hh, gh_p, 1536, 512);
    // 6. attention scores (profiled launch)
    mma3_scores<<<dim3(2, 512), 256, SMEM_SCORES>>>(xe_b, we_w);
    // 7. softmax + context + cc
    softmax_ctx_cc<<<B_, T_>>>(x, emb, yPrev);
    // 8. gi = cc @ w_ih^T + b_ih     [256,1536], K=1024
    mma3_gemm<false><<<dim3(6, 2), 256, SMEM_GEMM>>>(cch, ccl, ih_h, ih_l, b_ih, gi_p, 1536, 1024);
    // 9. GRU
    gru_kernel<<<B_, 256>>>(sPrev, h_out);
    // 10. logits = h @ fc_w^T + fc_b [256,6625]
    mma3_gemm<true><<<dim3(26, 2), 256, SMEM_GEMM>>>(hh2, hl2, fc_h, fc_l, fc_b, out, 6625, 512);
}

// round 6
// speedup vs baseline: 2.7607x; 1.3291x over previous
#include <cuda_runtime.h>
#include <cuda_bf16.h>
#include <math.h>
#include <stdint.h>

#define B_  256
#define T_  256
#define XD_ 512
#define SD_ 512
#define AD_ 512
#define YD_ 6625

// ---------------- scratch ----------------
__device__ float g_sProj[B_ * AD_];
__device__ float g_spart[2 * B_ * T_];
__device__ float g_gi[B_ * 3 * SD_];
__device__ float g_gh[B_ * 3 * SD_];

__device__ __nv_bfloat16 g_sh[B_ * SD_],   g_sl[B_ * SD_];
__device__ __nv_bfloat16 g_cch[B_ * 1024], g_ccl[B_ * 1024];
__device__ __nv_bfloat16 g_hh2[B_ * SD_],  g_hl2[B_ * SD_];

__device__ __nv_bfloat16 g_xe_h[512 * 512],   g_xe_l[512 * 512];
__device__ __nv_bfloat16 g_se_h[512 * 512],   g_se_l[512 * 512];
__device__ __nv_bfloat16 g_hh_h[1536 * 512],  g_hh_l[1536 * 512];
__device__ __nv_bfloat16 g_ih_h[1536 * 1024], g_ih_l[1536 * 1024];
__device__ __nv_bfloat16 g_fc_h[6625 * 512],  g_fc_l[6625 * 512];

// ---------------- helpers ----------------
__device__ __forceinline__ uint32_t smem_u32(const void* p) {
    uint32_t a;
    asm("{ .reg .u64 t; cvta.to.shared.u64 t, %1; cvt.u32.u64 %0, t; }" : "=r"(a) : "l"(p));
    return a;
}
__device__ __forceinline__ void ldmx4(uint32_t addr, uint32_t* r) {
    asm volatile("ldmatrix.sync.aligned.m8n8.x4.shared.b16 {%0,%1,%2,%3}, [%4];"
        : "=r"(r[0]), "=r"(r[1]), "=r"(r[2]), "=r"(r[3]) : "r"(addr));
}
__device__ __forceinline__ void mma_bf16(float* c, const uint32_t* a, uint32_t b0, uint32_t b1) {
    asm volatile("mma.sync.aligned.m16n8k16.row.col.f32.bf16.bf16.f32 "
        "{%0,%1,%2,%3}, {%4,%5,%6,%7}, {%8,%9}, {%0,%1,%2,%3};"
        : "+f"(c[0]), "+f"(c[1]), "+f"(c[2]), "+f"(c[3])
        : "r"(a[0]), "r"(a[1]), "r"(a[2]), "r"(a[3]), "r"(b0), "r"(b1));
}
__device__ __forceinline__ void cpa16(uint32_t dst, const void* src) {
    asm volatile("cp.async.cg.shared.global [%0], [%1], 16;" :: "r"(dst), "l"(src) : "memory");
}
#define CP_COMMIT() asm volatile("cp.async.commit_group;" ::: "memory")
#define CP_WAIT(n)  asm volatile("cp.async.wait_group %0;" :: "n"(n) : "memory")

__device__ __forceinline__ float tanh_fast(float x) {
    float xc = fminf(fmaxf(x, -15.f), 15.f);
    float e = exp2f(xc * 2.8853900817779268f);
    return __fdividef(e - 1.0f, e + 1.0f);
}
__device__ __forceinline__ uint32_t pack_hi_lo(float a, float b, uint32_t& lo) {
    __nv_bfloat16 ha = __float2bfloat16(a), hb = __float2bfloat16(b);
    __nv_bfloat16 la = __float2bfloat16(a - __bfloat162float(ha));
    __nv_bfloat16 lb = __float2bfloat16(b - __bfloat162float(hb));
    lo = (uint32_t)*(unsigned short*)&la | ((uint32_t)*(unsigned short*)&lb << 16);
    return (uint32_t)*(unsigned short*)&ha | ((uint32_t)*(unsigned short*)&hb << 16);
}

// ---------------- smem layouts ----------------
#define APAD       80
// scores kernel: A 128 rows, 3 stages
#define A128_HL    (128 * APAD)
#define A128_STG   (2 * A128_HL)       // 20480
#define W_HL       (256 * APAD)        // 20480
#define W_STG      (2 * W_HL)          // 40960
#define STG3       (A128_STG + W_STG)  // 61440
#define SM3_TAB    (3 * STG3)          // 184320
#define SMEM_SCORES (SM3_TAB + 4096)
// small gemm: A 64 rows, 4 stages
#define A64_HL     (64 * APAD)
#define A64_STG    (2 * A64_HL)        // 10240
#define STG4       (A64_STG + W_STG)   // 51200
#define SMEM_GEMM  (4 * STG4)          // 204800

// ================= small GEMM (64x256 tile, 4 stages) =================
template<bool GUARD>
__device__ __forceinline__ void load_stage4(char* smc, uint32_t sm, int stage,
        const __nv_bfloat16* Ah, const __nv_bfloat16* Al,
        const __nv_bfloat16* Wh, const __nv_bfloat16* Wl,
        int m0, int nb, int N, int K, int c, int tid)
{
    uint32_t base = sm + stage * STG4;
    int k0 = c * 32;
    #pragma unroll
    for (int it = 0; it < 2; ++it) {             // A: 64 rows
        int idx = it * 256 + tid;
        int hl = idx >> 8, rem = idx & 255, r = rem >> 2, c4 = rem & 3;
        cpa16(base + hl * A64_HL + r * APAD + c4 * 16,
              (hl ? Al : Ah) + (size_t)(m0 + r) * K + k0 + c4 * 8);
    }
    #pragma unroll
    for (int it = 0; it < 8; ++it) {             // W: 256 rows
        int idx = it * 256 + tid;
        int hl = idx >> 10, rem = idx & 1023, r = rem >> 2, c4 = rem & 3;
        uint32_t dst = base + A64_STG + hl * W_HL + r * APAD + c4 * 16;
        if (!GUARD || (nb + r) < N)
            cpa16(dst, (hl ? Wl : Wh) + (size_t)(nb + r) * K + k0 + c4 * 8);
        else
            *(uint4*)(smc + (dst - sm)) = make_uint4(0, 0, 0, 0);
    }
}

__device__ __forceinline__ void compute_chunk4(uint32_t sm, int stage, int lane,
                                               int wm, int wn, float (&acc)[2][8][4])
{
    uint32_t aB = sm + stage * STG4;
    uint32_t wB = aB + A64_STG;
    #pragma unroll
    for (int ks = 0; ks < 2; ++ks) {
        uint32_t Ah[2][4], Al[2][4];
        #pragma unroll
        for (int mt = 0; mt < 2; ++mt) {
            uint32_t aoff = (uint32_t)(wm + mt * 16 + (lane & 15)) * APAD
                          + (uint32_t)(ks * 2 + (lane >> 4)) * 16;
            ldmx4(aB + aoff, Ah[mt]);
            ldmx4(aB + A64_HL + aoff, Al[mt]);
        }
        #pragma unroll
        for (int g = 0; g < 4; ++g) {
            uint32_t bh[4], bl[4];
            uint32_t boff = (uint32_t)(wn + g * 16 + ((lane >> 4) << 3) + (lane & 7)) * APAD
                          + (uint32_t)(ks * 2 + ((lane >> 3) & 1)) * 16;
            ldmx4(wB + boff, bh);
            ldmx4(wB + W_HL + boff, bl);
            #pragma unroll
            for (int mt = 0; mt < 2; ++mt)
                #pragma unroll
                for (int h = 0; h < 2; ++h) {
                    float* c = acc[mt][g * 2 + h];
                    mma_bf16(c, Ah[mt], bh[2 * h], bh[2 * h + 1]);
                    mma_bf16(c, Al[mt], bh[2 * h], bh[2 * h + 1]);
                    mma_bf16(c, Ah[mt], bl[2 * h], bl[2 * h + 1]);
                }
        }
    }
}

template<bool GUARD>
__global__ void __launch_bounds__(256, 1)
mma4_gemm(const __nv_bfloat16* __restrict__ Ah, const __nv_bfloat16* __restrict__ Al,
          const __nv_bfloat16* __restrict__ Wh, const __nv_bfloat16* __restrict__ Wl,
          const float* __restrict__ bias, float* __restrict__ C, int N, int K)
{
    extern __shared__ char smc[];
    uint32_t sm = smem_u32(smc);
    int tid = threadIdx.x, lane = tid & 31, wid = tid >> 5;
    int wm = (wid >> 2) * 32, wn = (wid & 3) * 64;
    int m0 = blockIdx.y * 64, nb = blockIdx.x * 256;

    float acc[2][8][4] = {};
    int NC = K >> 5;
    load_stage4<GUARD>(smc, sm, 0, Ah, Al, Wh, Wl, m0, nb, N, K, 0, tid); CP_COMMIT();
    load_stage4<GUARD>(smc, sm, 1, Ah, Al, Wh, Wl, m0, nb, N, K, 1, tid); CP_COMMIT();
    load_stage4<GUARD>(smc, sm, 2, Ah, Al, Wh, Wl, m0, nb, N, K, 2, tid); CP_COMMIT();
    for (int c = 0; c < NC; ++c) {
        int r = NC - 1 - c;
        if (r >= 2) CP_WAIT(2); else if (r == 1) CP_WAIT(1); else CP_WAIT(0);
        __syncthreads();
        if (c + 3 < NC) {
            load_stage4<GUARD>(smc, sm, (c + 3) & 3, Ah, Al, Wh, Wl, m0, nb, N, K, c + 3, tid);
            CP_COMMIT();
        }
        compute_chunk4(sm, c & 3, lane, wm, wn, acc);
    }

    #pragma unroll
    for (int mt = 0; mt < 2; ++mt) {
        int r1 = m0 + wm + mt * 16 + (lane >> 2), r2 = r1 + 8;
        #pragma unroll
        for (int nt = 0; nt < 8; ++nt) {
            int n = nb + wn + nt * 8 + 2 * (lane & 3);
            if (!GUARD || n < N) {
                float b0 = bias[n];
                C[(size_t)r1 * N + n] = acc[mt][nt][0] + b0;
                C[(size_t)r2 * N + n] = acc[mt][nt][2] + b0;
                if (!GUARD || n + 1 < N) {
                    float b1 = bias[n + 1];
                    C[(size_t)r1 * N + n + 1] = acc[mt][nt][1] + b1;
                    C[(size_t)r2 * N + n + 1] = acc[mt][nt][3] + b1;
                }
            }
        }
    }
}

// ================= scores kernel (128x256 tile, 3 stages, in-kernel A split) =================
__device__ __forceinline__ void loadW3(char* smc, uint32_t sm, int stage, int nb, int c, int tid)
{
    uint32_t base = sm + stage * STG3 + A128_STG;
    int k0 = c * 32;
    #pragma unroll
    for (int it = 0; it < 8; ++it) {
        int idx = it * 256 + tid;
        int hl = idx >> 10, rem = idx & 1023, r = rem >> 2, c4 = rem & 3;
        cpa16(base + hl * W_HL + r * APAD + c4 * 16,
              (hl ? g_xe_l : g_xe_h) + (size_t)(nb + r) * 512 + k0 + c4 * 8);
    }
}

__device__ __forceinline__ void ldgA_f32(float* R, const float* x, int m0, int c, int tid)
{
    const float4* p = (const float4*)(x + (size_t)(m0 + (tid >> 1)) * 512 + c * 32 + (tid & 1) * 16);
    ((float4*)R)[0] = p[0]; ((float4*)R)[1] = p[1];
    ((float4*)R)[2] = p[2]; ((float4*)R)[3] = p[3];
}
__device__ __forceinline__ void stsA_split(const float* R, char* smc, int stage, int tid)
{
    uint32_t h[8], l[8];
    #pragma unroll
    for (int i = 0; i < 8; i++) h[i] = pack_hi_lo(R[2 * i], R[2 * i + 1], l[i]);
    uint32_t base = stage * STG3;
    uint32_t off = (uint32_t)(tid >> 1) * APAD + (uint32_t)(tid & 1) * 32;
    *(uint4*)(smc + base + off)                 = make_uint4(h[0], h[1], h[2], h[3]);
    *(uint4*)(smc + base + off + 16)            = make_uint4(h[4], h[5], h[6], h[7]);
    *(uint4*)(smc + base + A128_HL + off)       = make_uint4(l[0], l[1], l[2], l[3]);
    *(uint4*)(smc + base + A128_HL + off + 16)  = make_uint4(l[4], l[5], l[6], l[7]);
}

__device__ __forceinline__ void compute_chunk3(uint32_t sm, int stage, int lane,
                                               int wm, int wn, float (&acc)[4][8][4])
{
    uint32_t aB = sm + stage * STG3;
    uint32_t wB = aB + A128_STG;
    #pragma unroll
    for (int ks = 0; ks < 2; ++ks) {
        uint32_t Ah[4][4], Al[4][4];
        #pragma unroll
        for (int mt = 0; mt < 4; ++mt) {
            uint32_t aoff = (uint32_t)(wm + mt * 16 + (lane & 15)) * APAD
                          + (uint32_t)(ks * 2 + (lane >> 4)) * 16;
            ldmx4(aB + aoff, Ah[mt]);
            ldmx4(aB + A128_HL + aoff, Al[mt]);
        }
        #pragma unroll
        for (int g = 0; g < 4; ++g) {
            uint32_t bh[4], bl[4];
            uint32_t boff = (uint32_t)(wn + g * 16 + ((lane >> 4) << 3) + (lane & 7)) * APAD
                          + (uint32_t)(ks * 2 + ((lane >> 3) & 1)) * 16;
            ldmx4(wB + boff, bh);
            ldmx4(wB + W_HL + boff, bl);
            #pragma unroll
            for (int mt = 0; mt < 4; ++mt)
                #pragma unroll
                for (int h = 0; h < 2; ++h) {
                    float* c = acc[mt][g * 2 + h];
                    mma_bf16(c, Ah[mt], bh[2 * h], bh[2 * h + 1]);
                    mma_bf16(c, Al[mt], bh[2 * h], bh[2 * h + 1]);
                    mma_bf16(c, Ah[mt], bl[2 * h], bl[2 * h + 1]);
                }
        }
    }
}

__global__ void __launch_bounds__(256, 1)
mma3_scores(const float* __restrict__ x,
            const float* __restrict__ xe_b, const float* __restrict__ we)
{
    extern __shared__ char smc[];
    uint32_t sm = smem_u32(smc);
    int tid = threadIdx.x, lane = tid & 31, wid = tid >> 5;
    int wm = (wid >> 2) * 64, wn = (wid & 3) * 64;
    int wx = wid & 3;
    int m0 = blockIdx.y * 128, nb = blockIdx.x * 256;
    int bidx = blockIdx.y >> 1;

    float* cb_s = (float*)(smc + SM3_TAB);
    float* we_s = cb_s + 256;
    float* part = we_s + 256;
    cb_s[tid] = xe_b[nb + tid] + g_sProj[bidx * 512 + nb + tid];
    we_s[tid] = we[nb + tid];

    float acc[4][8][4] = {};
    float R[16];
    const int NC = 16;

    loadW3(smc, sm, 0, nb, 0, tid); CP_COMMIT();
    loadW3(smc, sm, 1, nb, 1, tid); CP_COMMIT();
    ldgA_f32(R, x, m0, 0, tid);
    stsA_split(R, smc, 0, tid);
    ldgA_f32(R, x, m0, 1, tid);

    for (int c = 0; c < NC; ++c) {
        if (c < NC - 1) CP_WAIT(1); else CP_WAIT(0);
        __syncthreads();
        if (c + 2 < NC) { loadW3(smc, sm, (c + 2) % 3, nb, c + 2, tid); CP_COMMIT(); }
        compute_chunk3(sm, c % 3, lane, wm, wn, acc);
        if (c + 1 < NC) stsA_split(R, smc, (c + 1) % 3, tid);
        if (c + 2 < NC) ldgA_f32(R, x, m0, c + 2, tid);
    }

    #pragma unroll
    for (int mt = 0; mt < 4; ++mt) {
        float s1 = 0.f, s2 = 0.f;
        #pragma unroll
        for (int nt = 0; nt < 8; ++nt) {
            int n = wn + nt * 8 + 2 * (lane & 3);
            float c0 = cb_s[n], c1 = cb_s[n + 1];
            float w0 = we_s[n], w1 = we_s[n + 1];
            s1 += tanh_fast(acc[mt][nt][0] + c0) * w0 + tanh_fast(acc[mt][nt][1] + c1) * w1;
            s2 += tanh_fast(acc[mt][nt][2] + c0) * w0 + tanh_fast(acc[mt][nt][3] + c1) * w1;
        }
        s1 += __shfl_xor_sync(0xffffffffu, s1, 1); s1 += __shfl_xor_sync(0xffffffffu, s1, 2);
        s2 += __shfl_xor_sync(0xffffffffu, s2, 1); s2 += __shfl_xor_sync(0xffffffffu, s2, 2);
        if ((lane & 3) == 0) {
            int rl = wm + mt * 16 + (lane >> 2);
            part[wx * 128 + rl]     = s1;
            part[wx * 128 + rl + 8] = s2;
        }
    }
    __syncthreads();
    if (tid < 128)
        g_spart[blockIdx.x * (B_ * T_) + m0 + tid] =
            part[tid] + part[128 + tid] + part[256 + tid] + part[384 + tid];
}

// ---------------- splits ----------------
__device__ __forceinline__ void split4_at(const float* __restrict__ w,
                                          __nv_bfloat16* __restrict__ hi,
                                          __nv_bfloat16* __restrict__ lo, int i)
{
    float4 v = *(const float4*)(w + i);
    float f[4] = {v.x, v.y, v.z, v.w};
    unsigned short hb[4], lb[4];
    #pragma unroll
    for (int j = 0; j < 4; j++) {
        __nv_bfloat16 h = __float2bfloat16(f[j]);
        __nv_bfloat16 l = __float2bfloat16(f[j] - __bfloat162float(h));
        hb[j] = *(unsigned short*)&h; lb[j] = *(unsigned short*)&l;
    }
    *(uint2*)(hi + i) = make_uint2((uint32_t)hb[0] | ((uint32_t)hb[1] << 16),
                                   (uint32_t)hb[2] | ((uint32_t)hb[3] << 16));
    *(uint2*)(lo + i) = make_uint2((uint32_t)lb[0] | ((uint32_t)lb[1] << 16),
                                   (uint32_t)lb[2] | ((uint32_t)lb[3] << 16));
}

__global__ void split4(const float* __restrict__ w,
                       __nv_bfloat16* __restrict__ hi,
                       __nv_bfloat16* __restrict__ lo, int nquads)
{
    int q = blockIdx.x * blockDim.x + threadIdx.x;
    if (q < nquads) split4_at(w, hi, lo, q * 4);
}

#define Q_XE 65536
#define Q_SE 65536
#define Q_HH 196608
#define Q_IH 393216
#define Q_FC 848000
#define Q_TOT (Q_XE + Q_SE + Q_HH + Q_IH + Q_FC)
__global__ void split_weights(const float* xe, const float* se, const float* hh,
                              const float* ih, const float* fc)
{
    int q = blockIdx.x * blockDim.x + threadIdx.x;
    if (q >= Q_TOT) return;
    if (q < Q_XE) { split4_at(xe, g_xe_h, g_xe_l, q * 4); return; }
    q -= Q_XE;
    if (q < Q_SE) { split4_at(se, g_se_h, g_se_l, q * 4); return; }
    q -= Q_SE;
    if (q < Q_HH) { split4_at(hh, g_hh_h, g_hh_l, q * 4); return; }
    q -= Q_HH;
    if (q < Q_IH) { split4_at(ih, g_ih_h, g_ih_l, q * 4); return; }
    q -= Q_IH;
    split4_at(fc, g_fc_h, g_fc_l, q * 4);
}

// ---------------- fused softmax + context + cc ----------------
__global__ void softmax_ctx_cc(const float* __restrict__ x,
                               const float* __restrict__ emb,
                               const int* __restrict__ yPrev)
{
    int b = blockIdx.x, t = threadIdx.x;
    __shared__ float al[T_];
    __shared__ float red[T_];
    float v = g_spart[b * T_ + t] + g_spart[B_ * T_ + b * T_ + t];
    red[t] = v; __syncthreads();
    for (int s = T_ / 2; s; s >>= 1) { if (t < s) red[t] = fmaxf(red[t], red[t + s]); __syncthreads(); }
    float mx = red[0]; __syncthreads();
    float e = expf(v - mx);
    red[t] = e; __syncthreads();
    for (int s = T_ / 2; s; s >>= 1) { if (t < s) red[t] += red[t + s]; __syncthreads(); }
    al[t] = e / red[0];
    __syncthreads();

    const float* xb = x + (size_t)b * T_ * XD_;
    float c0 = 0.f, c1 = 0.f;
    #pragma unroll 4
    for (int tt = 0; tt < T_; ++tt) {
        float a = al[tt];
        float2 xv = *(const float2*)(xb + (size_t)tt * XD_ + 2 * t);
        c0 += a * xv.x; c1 += a * xv.y;
    }
    uint32_t lo, hi;
    hi = pack_hi_lo(c0, c1, lo);
    ((uint32_t*)(g_cch + b * 1024 + 512))[t] = hi;
    ((uint32_t*)(g_ccl + b * 1024 + 512))[t] = lo;

    int y = yPrev[b];
    float2 ev = *(const float2*)(emb + (size_t)y * AD_ + 2 * t);
    hi = pack_hi_lo(ev.x, ev.y, lo);
    ((uint32_t*)(g_cch + b * 1024))[t] = hi;
    ((uint32_t*)(g_ccl + b * 1024))[t] = lo;
}

// ---------------- GRU elementwise ----------------
__global__ void gru_kernel(const float* __restrict__ s, float* __restrict__ h_out)
{
    int b = blockIdx.x;
    for (int j = threadIdx.x; j < SD_; j += blockDim.x) {
        float ir = g_gi[b * 3 * SD_ + j];
        float iz = g_gi[b * 3 * SD_ + SD_ + j];
        float in_ = g_gi[b * 3 * SD_ + 2 * SD_ + j];
        float hr = g_gh[b * 3 * SD_ + j];
        float hz = g_gh[b * 3 * SD_ + SD_ + j];
        float hn = g_gh[b * 3 * SD_ + 2 * SD_ + j];
        float r = 1.f / (1.f + expf(-(ir + hr)));
        float z = 1.f / (1.f + expf(-(iz + hz)));
        float n = tanhf(in_ + r * hn);
        float hv = (1.f - z) * n + z * s[b * SD_ + j];
        __nv_bfloat16 hb = __float2bfloat16(hv);
        g_hh2[b * SD_ + j] = hb;
        g_hl2[b * SD_ + j] = __float2bfloat16(hv - __bfloat162float(hb));
        if (h_out) h_out[b * SD_ + j] = hv;
    }
}

// ======================================================================
extern "C" void kernel_launch(void* const* d_in, const int* in_sizes, int n_in,
                              void* d_out, int out_size)
{
    const float* x     = (const float*)d_in[0];
    const float* sPrev = (const float*)d_in[1];
    const int*   yPrev = (const int*)  d_in[2];
    const float* xe_w  = (const float*)d_in[3];
    const float* xe_b  = (const float*)d_in[4];
    const float* se_w  = (const float*)d_in[5];
    const float* se_b  = (const float*)d_in[6];
    const float* we_w  = (const float*)d_in[7];
    const float* emb   = (const float*)d_in[9];
    const float* w_ih  = (const float*)d_in[10];
    const float* w_hh  = (const float*)d_in[11];
    const float* b_ih  = (const float*)d_in[12];
    const float* b_hh  = (const float*)d_in[13];
    const float* fc_w  = (const float*)d_in[14];
    const float* fc_b  = (const float*)d_in[15];

    float* out = (float*)d_out;
    float* h_out = (out_size >= B_ * YD_ + B_ * SD_) ? out + (size_t)B_ * YD_ : nullptr;

    float *sProj_p, *gi_p, *gh_p;
    cudaGetSymbolAddress((void**)&sProj_p, g_sProj);
    cudaGetSymbolAddress((void**)&gi_p, g_gi);
    cudaGetSymbolAddress((void**)&gh_p, g_gh);
    __nv_bfloat16 *sh, *sl, *cch, *ccl, *hh2, *hl2;
    cudaGetSymbolAddress((void**)&sh, g_sh);   cudaGetSymbolAddress((void**)&sl, g_sl);
    cudaGetSymbolAddress((void**)&cch, g_cch); cudaGetSymbolAddress((void**)&ccl, g_ccl);
    cudaGetSymbolAddress((void**)&hh2, g_hh2); cudaGetSymbolAddress((void**)&hl2, g_hl2);
    __nv_bfloat16 *se_h, *se_l, *hh_h, *hh_l, *ih_h, *ih_l, *fc_h, *fc_l;
    cudaGetSymbolAddress((void**)&se_h, g_se_h); cudaGetSymbolAddress((void**)&se_l, g_se_l);
    cudaGetSymbolAddress((void**)&hh_h, g_hh_h); cudaGetSymbolAddress((void**)&hh_l, g_hh_l);
    cudaGetSymbolAddress((void**)&ih_h, g_ih_h); cudaGetSymbolAddress((void**)&ih_l, g_ih_l);
    cudaGetSymbolAddress((void**)&fc_h, g_fc_h); cudaGetSymbolAddress((void**)&fc_l, g_fc_l);

    static cudaStream_t s2 = nullptr;
    static cudaEvent_t evW = nullptr, evGH = nullptr;
    if (!s2) {
        cudaFuncSetAttribute(mma3_scores,      cudaFuncAttributeMaxDynamicSharedMemorySize, SMEM_SCORES);
        cudaFuncSetAttribute(mma4_gemm<false>, cudaFuncAttributeMaxDynamicSharedMemorySize, SMEM_GEMM);
        cudaFuncSetAttribute(mma4_gemm<true>,  cudaFuncAttributeMaxDynamicSharedMemorySize, SMEM_GEMM);
        cudaStreamCreateWithFlags(&s2, cudaStreamNonBlocking);
        cudaEventCreateWithFlags(&evW, cudaEventDisableTiming);
        cudaEventCreateWithFlags(&evGH, cudaEventDisableTiming);
    }

    #define CEIL_DIV(a, b) (((a) + (b) - 1) / (b))

    // prologue
    split4<<<CEIL_DIV(B_ * SD_ / 4, 256), 256>>>(sPrev, sh, sl, B_ * SD_ / 4);
    split_weights<<<CEIL_DIV(Q_TOT, 256), 256>>>(xe_w, se_w, w_hh, w_ih, fc_w);
    cudaEventRecord(evW, 0);

    // fork: gh on stream s2 (joined before gru)
    cudaStreamWaitEvent(s2, evW, 0);
    mma4_gemm<false><<<dim3(6, 4), 256, SMEM_GEMM, s2>>>(sh, sl, hh_h, hh_l, b_hh, gh_p, 1536, 512);
    cudaEventRecord(evGH, s2);

    // main chain
    mma4_gemm<false><<<dim3(2, 4), 256, SMEM_GEMM>>>(sh, sl, se_h, se_l, se_b, sProj_p, 512, 512);
    mma3_scores<<<dim3(2, 512), 256, SMEM_SCORES>>>(x, xe_b, we_w);
    softmax_ctx_cc<<<B_, T_>>>(x, emb, yPrev);
    mma4_gemm<false><<<dim3(6, 4), 256, SMEM_GEMM>>>(cch, ccl, ih_h, ih_l, b_ih, gi_p, 1536, 1024);
    cudaStreamWaitEvent(0, evGH, 0);
    gru_kernel<<<B_, 256>>>(sPrev, h_out);
    mma4_gemm<true><<<dim3(26, 4), 256, SMEM_GEMM>>>(hh2, hl2, fc_h, fc_l, fc_b, out, 6625, 512);
}

// round 8
// speedup vs baseline: 3.2085x; 1.1622x over previous
#include <cuda_runtime.h>
#include <cuda_bf16.h>
#include <math.h>
#include <stdint.h>

#define B_  256
#define T_  256
#define YD_ 6625

// ---------------- fp32 scratch ----------------
__device__ float g_sProj[256 * 512];
__device__ float g_spart[2 * 65536];
__device__ float g_gi[256 * 1536];
__device__ float g_gh[256 * 1536];

// ---------------- chunk-tiled, pre-swizzled bf16 scratch ----------------
// layout: slab(c, plane) = base + (c*2+plane)*Rpad*32 elems; row r at +r*32 elems (64B);
// within row, 16B unit j stored at (j ^ ((r>>1)&3)).
__device__ __nv_bfloat16 g_x_t [16u * 2 * 65536 * 32];
__device__ __nv_bfloat16 g_s_t [16 * 2 * 256 * 32];
__device__ __nv_bfloat16 g_cc_t[32 * 2 * 256 * 32];
__device__ __nv_bfloat16 g_h_t [16 * 2 * 256 * 32];
__device__ __nv_bfloat16 g_xe_t[16 * 2 * 512 * 32];
__device__ __nv_bfloat16 g_se_t[16 * 2 * 512 * 32];
__device__ __nv_bfloat16 g_hh_t[16 * 2 * 1536 * 32];
__device__ __nv_bfloat16 g_ih_t[32 * 2 * 1536 * 32];
__device__ __nv_bfloat16 g_fc_t[16 * 2 * 6656 * 32];

// ---------------- helpers ----------------
__device__ __forceinline__ uint32_t smem_u32(const void* p) {
    uint32_t a;
    asm("{ .reg .u64 t; cvta.to.shared.u64 t, %1; cvt.u32.u64 %0, t; }" : "=r"(a) : "l"(p));
    return a;
}
__device__ __forceinline__ void ldmx4(uint32_t addr, uint32_t* r) {
    asm volatile("ldmatrix.sync.aligned.m8n8.x4.shared.b16 {%0,%1,%2,%3}, [%4];"
        : "=r"(r[0]), "=r"(r[1]), "=r"(r[2]), "=r"(r[3]) : "r"(addr));
}
__device__ __forceinline__ void mma_bf16(float* c, const uint32_t* a, uint32_t b0, uint32_t b1) {
    asm volatile("mma.sync.aligned.m16n8k16.row.col.f32.bf16.bf16.f32 "
        "{%0,%1,%2,%3}, {%4,%5,%6,%7}, {%8,%9}, {%0,%1,%2,%3};"
        : "+f"(c[0]), "+f"(c[1]), "+f"(c[2]), "+f"(c[3])
        : "r"(a[0]), "r"(a[1]), "r"(a[2]), "r"(a[3]), "r"(b0), "r"(b1));
}
#define MBAR_INIT(mb, c) asm volatile("mbarrier.init.shared.b64 [%0], %1;" :: "r"(mb), "r"(c) : "memory")
#define MB_EXPECT(mb, n) asm volatile("mbarrier.arrive.expect_tx.shared.b64 _, [%0], %1;" :: "r"(mb), "r"(n) : "memory")
#define FENCE_ASYNC()    asm volatile("fence.proxy.async.shared::cta;" ::: "memory")
#define BULK_G2S(dst, src, sz, mb) \
    asm volatile("cp.async.bulk.shared::cluster.global.mbarrier::complete_tx::bytes [%0], [%1], %2, [%3];" \
        :: "r"(dst), "l"(src), "r"(sz), "r"(mb) : "memory")

__device__ __forceinline__ void mbar_wait(uint32_t mb, uint32_t phase) {
    asm volatile(
        "{\n\t.reg .pred P;\n\t"
        "WL%=:\n\t"
        "mbarrier.try_wait.parity.acquire.cta.shared::cta.b64 P, [%0], %1, 0x989680;\n\t"
        "@!P bra WL%=;\n\t}"
        :: "r"(mb), "r"(phase) : "memory");
}

__device__ __forceinline__ float tanh_fast(float x) {
    float xc = fminf(fmaxf(x, -15.f), 15.f);
    float e = exp2f(xc * 2.8853900817779268f);
    return __fdividef(e - 1.0f, e + 1.0f);
}
__device__ __forceinline__ uint32_t pack_hi_lo(float a, float b, uint32_t& lo) {
    __nv_bfloat16 ha = __float2bfloat16(a), hb = __float2bfloat16(b);
    __nv_bfloat16 la = __float2bfloat16(a - __bfloat162float(ha));
    __nv_bfloat16 lb = __float2bfloat16(b - __bfloat162float(hb));
    lo = (uint32_t)*(unsigned short*)&la | ((uint32_t)*(unsigned short*)&lb << 16);
    return (uint32_t)*(unsigned short*)&ha | ((uint32_t)*(unsigned short*)&hb << 16);
}

// ---------------- split writers ----------------
__device__ __forceinline__ void split_unit(const float* __restrict__ w,
                                           __nv_bfloat16* __restrict__ out,
                                           int Rpad, int K, int u)
{
    int upr = K >> 3;
    int r = u / upr, uu = u - r * upr;
    int c = uu >> 2, j = uu & 3;
    const float4* src = (const float4*)(w + (size_t)r * K + c * 32 + j * 8);
    float4 v0 = src[0], v1 = src[1];
    float f[8] = {v0.x, v0.y, v0.z, v0.w, v1.x, v1.y, v1.z, v1.w};
    uint32_t h[4], l[4];
    #pragma unroll
    for (int i = 0; i < 4; i++) h[i] = pack_hi_lo(f[2 * i], f[2 * i + 1], l[i]);
    size_t slab = ((size_t)(c * 2) * Rpad + r) * 32;
    uint32_t sw = (uint32_t)(j ^ ((r >> 1) & 3)) << 4;
    *(uint4*)((char*)(out + slab) + sw) = make_uint4(h[0], h[1], h[2], h[3]);
    *(uint4*)((char*)(out + slab) + (size_t)Rpad * 64 + sw) = make_uint4(l[0], l[1], l[2], l[3]);
}

__global__ void split_gen(const float* __restrict__ w, __nv_bfloat16* __restrict__ out,
                          int Rpad, int K, int nunits)
{
    int u = blockIdx.x * blockDim.x + threadIdx.x;
    if (u < nunits) split_unit(w, out, Rpad, K, u);
}

__global__ void split_weights(const float* xe, const float* se, const float* hh,
                              const float* ih, const float* fc)
{
    int u = blockIdx.x * blockDim.x + threadIdx.x;
    if (u < 32768)  { split_unit(xe, g_xe_t, 512, 512, u); return; }  u -= 32768;
    if (u < 32768)  { split_unit(se, g_se_t, 512, 512, u); return; }  u -= 32768;
    if (u < 98304)  { split_unit(hh, g_hh_t, 1536, 512, u); return; } u -= 98304;
    if (u < 196608) { split_unit(ih, g_ih_t, 1536, 1024, u); return; } u -= 196608;
    if (u < 424000) { split_unit(fc, g_fc_t, 6656, 512, u); }
}

// tiled scalar-pair writer (for cc / h producers)
__device__ __forceinline__ void store_pair_tiled(__nv_bfloat16* base, int Rpad,
                                                 int r, int col, float v0, float v1)
{
    uint32_t lo, hi = pack_hi_lo(v0, v1, lo);
    int c = col >> 5, k = col & 31, j = k >> 3;
    size_t slab = ((size_t)(c * 2) * Rpad + r) * 32;
    uint32_t sw = ((uint32_t)(j ^ ((r >> 1) & 3)) << 4) + (k & 7) * 2;
    *(uint32_t*)((char*)(base + slab) + sw) = hi;
    *(uint32_t*)((char*)(base + slab) + (size_t)Rpad * 64 + sw) = lo;
}

// ---------------- bulk-loaded GEMM (M-tile 64, N-tile 256, 3 stages) ----------------
#define STG_G   40960
#define MB_G    (3 * STG_G)
#define SMEM_G  (MB_G + 64)

__device__ __forceinline__ void issue64(uint32_t stbase, uint32_t mb,
        const __nv_bfloat16* At, int RpadA, int m0,
        const __nv_bfloat16* Wt, int RpadW, int nb, int chunk)
{
    MB_EXPECT(mb, 40960u);
    const char* a0 = (const char*)(At + ((size_t)(chunk * 2 + 0) * RpadA + m0) * 32);
    const char* a1 = (const char*)(At + ((size_t)(chunk * 2 + 1) * RpadA + m0) * 32);
    const char* w0 = (const char*)(Wt + ((size_t)(chunk * 2 + 0) * RpadW + nb) * 32);
    const char* w1 = (const char*)(Wt + ((size_t)(chunk * 2 + 1) * RpadW + nb) * 32);
    BULK_G2S(stbase,          a0, 4096u,  mb);
    BULK_G2S(stbase + 4096,   a1, 4096u,  mb);
    BULK_G2S(stbase + 8192,   w0, 16384u, mb);
    BULK_G2S(stbase + 24576,  w1, 16384u, mb);
}

__device__ __forceinline__ void cchunk64(uint32_t aB, uint32_t wB, int lane,
                                         int wm, int wn, float (&acc)[2][8][4])
{
    #pragma unroll
    for (int ks = 0; ks < 2; ++ks) {
        uint32_t Ah[2][4], Al[2][4];
        #pragma unroll
        for (int mt = 0; mt < 2; ++mt) {
            int row = wm + mt * 16 + (lane & 15);
            uint32_t col = (uint32_t)((ks * 2 + (lane >> 4)) ^ ((row >> 1) & 3));
            uint32_t off = (uint32_t)row * 64 + col * 16;
            ldmx4(aB + off, Ah[mt]);
            ldmx4(aB + 4096 + off, Al[mt]);
        }
        #pragma unroll
        for (int g = 0; g < 4; ++g) {
            int row = wn + g * 16 + ((lane >> 4) << 3) + (lane & 7);
            uint32_t col = (uint32_t)((ks * 2 + ((lane >> 3) & 1)) ^ ((row >> 1) & 3));
            uint32_t off = (uint32_t)row * 64 + col * 16;
            uint32_t bh[4], bl[4];
            ldmx4(wB + off, bh);
            ldmx4(wB + 16384 + off, bl);
            #pragma unroll
            for (int mt = 0; mt < 2; ++mt)
                #pragma unroll
                for (int h = 0; h < 2; ++h) {
                    float* c = acc[mt][g * 2 + h];
                    mma_bf16(c, Ah[mt], bh[2 * h], bh[2 * h + 1]);
                    mma_bf16(c, Al[mt], bh[2 * h], bh[2 * h + 1]);
                    mma_bf16(c, Ah[mt], bl[2 * h], bl[2 * h + 1]);
                }
        }
    }
}

template<bool GUARD>
__global__ void __launch_bounds__(256, 1)
bulk_gemm(const __nv_bfloat16* __restrict__ At, int RpadA,
          const __nv_bfloat16* __restrict__ Wt, int RpadW,
          const float* __restrict__ bias, float* __restrict__ C, int N, int K)
{
    extern __shared__ char smc[];
    uint32_t sm = smem_u32(smc);
    int tid = threadIdx.x, lane = tid & 31, wid = tid >> 5;
    int wm = (wid >> 2) * 32, wn = (wid & 3) * 64;
    int m0 = blockIdx.y * 64, nb = blockIdx.x * 256;
    uint32_t mb = sm + MB_G;
    int NC = K >> 5;

    if (tid == 0) {
        for (int s = 0; s < 3; s++) MBAR_INIT(mb + 8 * s, 1);
    }
    __syncthreads();
    if (tid == 0) {
        FENCE_ASYNC();
        for (int s = 0; s < 3; s++)
            issue64(sm + s * STG_G, mb + 8 * s, At, RpadA, m0, Wt, RpadW, nb, s);
    }

    float acc[2][8][4] = {};
    for (int c = 0; c < NC; ++c) {
        int st = c % 3;
        mbar_wait(mb + 8 * st, (uint32_t)((c / 3) & 1));
        cchunk64(sm + st * STG_G, sm + st * STG_G + 8192, lane, wm, wn, acc);
        __syncthreads();
        if (tid == 0 && c + 3 < NC) {
            FENCE_ASYNC();
            issue64(sm + st * STG_G, mb + 8 * st, At, RpadA, m0, Wt, RpadW, nb, c + 3);
        }
    }

    #pragma unroll
    for (int mt = 0; mt < 2; ++mt) {
        int r1 = m0 + wm + mt * 16 + (lane >> 2), r2 = r1 + 8;
        #pragma unroll
        for (int nt = 0; nt < 8; ++nt) {
            int n = nb + wn + nt * 8 + 2 * (lane & 3);
            if (!GUARD || n < N) {
                float b0 = bias[n];
                C[(size_t)r1 * N + n] = acc[mt][nt][0] + b0;
                C[(size_t)r2 * N + n] = acc[mt][nt][2] + b0;
                if (!GUARD || n + 1 < N) {
                    float b1 = bias[n + 1];
                    C[(size_t)r1 * N + n + 1] = acc[mt][nt][1] + b1;
                    C[(size_t)r2 * N + n + 1] = acc[mt][nt][3] + b1;
                }
            }
        }
    }
}

// ---------------- scores kernel (M-tile 128, N-tile 256, 3 stages) ----------------
#define STG_S   49152
#define TAB_S   (3 * STG_S)
#define MB_S    (TAB_S + 4096)
#define SMEM_S  (MB_S + 64)

__device__ __forceinline__ void issue128(uint32_t stbase, uint32_t mb, int m0, int nb, int chunk)
{
    MB_EXPECT(mb, 49152u);
    const char* a0 = (const char*)(g_x_t + ((size_t)(chunk * 2 + 0) * 65536 + m0) * 32);
    const char* a1 = (const char*)(g_x_t + ((size_t)(chunk * 2 + 1) * 65536 + m0) * 32);
    const char* w0 = (const char*)(g_xe_t + ((size_t)(chunk * 2 + 0) * 512 + nb) * 32);
    const char* w1 = (const char*)(g_xe_t + ((size_t)(chunk * 2 + 1) * 512 + nb) * 32);
    BULK_G2S(stbase,          a0, 8192u,  mb);
    BULK_G2S(stbase + 8192,   a1, 8192u,  mb);
    BULK_G2S(stbase + 16384,  w0, 16384u, mb);
    BULK_G2S(stbase + 32768,  w1, 16384u, mb);
}

__device__ __forceinline__ void cchunk128(uint32_t aB, uint32_t wB, int lane,
                                          int wm, int wn, float (&acc)[4][8][4])
{
    #pragma unroll
    for (int ks = 0; ks < 2; ++ks) {
        uint32_t Ah[4][4], Al[4][4];
        #pragma unroll
        for (int mt = 0; mt < 4; ++mt) {
            int row = wm + mt * 16 + (lane & 15);
            uint32_t col = (uint32_t)((ks * 2 + (lane >> 4)) ^ ((row >> 1) & 3));
            uint32_t off = (uint32_t)row * 64 + col * 16;
            ldmx4(aB + off, Ah[mt]);
            ldmx4(aB + 8192 + off, Al[mt]);
        }
        #pragma unroll
        for (int g = 0; g < 4; ++g) {
            int row = wn + g * 16 + ((lane >> 4) << 3) + (lane & 7);
            uint32_t col = (uint32_t)((ks * 2 + ((lane >> 3) & 1)) ^ ((row >> 1) & 3));
            uint32_t off = (uint32_t)row * 64 + col * 16;
            uint32_t bh[4], bl[4];
            ldmx4(wB + off, bh);
            ldmx4(wB + 16384 + off, bl);
            #pragma unroll
            for (int mt = 0; mt < 4; ++mt)
                #pragma unroll
                for (int h = 0; h < 2; ++h) {
                    float* c = acc[mt][g * 2 + h];
                    mma_bf16(c, Ah[mt], bh[2 * h], bh[2 * h + 1]);
                    mma_bf16(c, Al[mt], bh[2 * h], bh[2 * h + 1]);
                    mma_bf16(c, Ah[mt], bl[2 * h], bl[2 * h + 1]);
                }
        }
    }
}

__global__ void __launch_bounds__(256, 1)
bulk_scores(const float* __restrict__ xe_b, const float* __restrict__ we)
{
    extern __shared__ char smc[];
    uint32_t sm = smem_u32(smc);
    int tid = threadIdx.x, lane = tid & 31, wid = tid >> 5;
    int wm = (wid >> 2) * 64, wn = (wid & 3) * 64;
    int wx = wid & 3;
    int m0 = blockIdx.y * 128, nb = blockIdx.x * 256;
    int bidx = blockIdx.y >> 1;
    uint32_t mb = sm + MB_S;

    float* cb_s = (float*)(smc + TAB_S);
    float* we_s = cb_s + 256;
    float* part = we_s + 256;
    cb_s[tid] = xe_b[nb + tid] + g_sProj[bidx * 512 + nb + tid];
    we_s[tid] = we[nb + tid];

    if (tid == 0) {
        for (int s = 0; s < 3; s++) MBAR_INIT(mb + 8 * s, 1);
    }
    __syncthreads();
    if (tid == 0) {
        FENCE_ASYNC();
        for (int s = 0; s < 3; s++)
            issue128(sm + s * STG_S, mb + 8 * s, m0, nb, s);
    }

    float acc[4][8][4] = {};
    const int NC = 16;
    for (int c = 0; c < NC; ++c) {
        int st = c % 3;
        mbar_wait(mb + 8 * st, (uint32_t)((c / 3) & 1));
        cchunk128(sm + st * STG_S, sm + st * STG_S + 16384, lane, wm, wn, acc);
        __syncthreads();
        if (tid == 0 && c + 3 < NC) {
            FENCE_ASYNC();
            issue128(sm + st * STG_S, mb + 8 * st, m0, nb, c + 3);
        }
    }

    #pragma unroll
    for (int mt = 0; mt < 4; ++mt) {
        float s1 = 0.f, s2 = 0.f;
        #pragma unroll
        for (int nt = 0; nt < 8; ++nt) {
            int n = wn + nt * 8 + 2 * (lane & 3);
            float c0 = cb_s[n], c1 = cb_s[n + 1];
            float w0 = we_s[n], w1 = we_s[n + 1];
            s1 += tanh_fast(acc[mt][nt][0] + c0) * w0 + tanh_fast(acc[mt][nt][1] + c1) * w1;
            s2 += tanh_fast(acc[mt][nt][2] + c0) * w0 + tanh_fast(acc[mt][nt][3] + c1) * w1;
        }
        s1 += __shfl_xor_sync(0xffffffffu, s1, 1); s1 += __shfl_xor_sync(0xffffffffu, s1, 2);
        s2 += __shfl_xor_sync(0xffffffffu, s2, 1); s2 += __shfl_xor_sync(0xffffffffu, s2, 2);
        if ((lane & 3) == 0) {
            int rl = wm + mt * 16 + (lane >> 2);
            part[wx * 128 + rl]     = s1;
            part[wx * 128 + rl + 8] = s2;
        }
    }
    __syncthreads();
    if (tid < 128)
        g_spart[blockIdx.x * 65536 + m0 + tid] =
            part[tid] + part[128 + tid] + part[256 + tid] + part[384 + tid];
}

// ---------------- fused softmax + context + cc (tiled output) ----------------
__global__ void softmax_ctx_cc(const float* __restrict__ x,
                               const float* __restrict__ emb,
                               const int* __restrict__ yPrev)
{
    int b = blockIdx.x, t = threadIdx.x;
    __shared__ float al[T_];
    __shared__ float red[T_];
    float v = g_spart[b * 256 + t] + g_spart[65536 + b * 256 + t];
    red[t] = v; __syncthreads();
    for (int s = 128; s; s >>= 1) { if (t < s) red[t] = fmaxf(red[t], red[t + s]); __syncthreads(); }
    float mx = red[0]; __syncthreads();
    float e = expf(v - mx);
    red[t] = e; __syncthreads();
    for (int s = 128; s; s >>= 1) { if (t < s) red[t] += red[t + s]; __syncthreads(); }
    al[t] = e / red[0];
    __syncthreads();

    const float* xb = x + (size_t)b * 256 * 512;
    float c0 = 0.f, c1 = 0.f;
    #pragma unroll 4
    for (int tt = 0; tt < 256; ++tt) {
        float a = al[tt];
        float2 xv = *(const float2*)(xb + (size_t)tt * 512 + 2 * t);
        c0 += a * xv.x; c1 += a * xv.y;
    }
    store_pair_tiled(g_cc_t, 256, b, 512 + 2 * t, c0, c1);

    int y = yPrev[b];
    float2 ev = *(const float2*)(emb + (size_t)y * 512 + 2 * t);
    store_pair_tiled(g_cc_t, 256, b, 2 * t, ev.x, ev.y);
}

// ---------------- GRU elementwise (tiled h output) ----------------
__global__ void gru_kernel(const float* __restrict__ s, float* __restrict__ h_out)
{
    int b = blockIdx.x, t = threadIdx.x;
    float hv[2];
    #pragma unroll
    for (int q = 0; q < 2; ++q) {
        int j = 2 * t + q;
        float ir = g_gi[b * 1536 + j];
        float iz = g_gi[b * 1536 + 512 + j];
        float in_ = g_gi[b * 1536 + 1024 + j];
        float hr = g_gh[b * 1536 + j];
        float hz = g_gh[b * 1536 + 512 + j];
        float hn = g_gh[b * 1536 + 1024 + j];
        float r = 1.f / (1.f + expf(-(ir + hr)));
        float z = 1.f / (1.f + expf(-(iz + hz)));
        float n = tanhf(in_ + r * hn);
        hv[q] = (1.f - z) * n + z * s[b * 512 + j];
        if (h_out) h_out[b * 512 + j] = hv[q];
    }
    store_pair_tiled(g_h_t, 256, b, 2 * t, hv[0], hv[1]);
}

// ======================================================================
extern "C" void kernel_launch(void* const* d_in, const int* in_sizes, int n_in,
                              void* d_out, int out_size)
{
    const float* x     = (const float*)d_in[0];
    const float* sPrev = (const float*)d_in[1];
    const int*   yPrev = (const int*)  d_in[2];
    const float* xe_w  = (const float*)d_in[3];
    const float* xe_b  = (const float*)d_in[4];
    const float* se_w  = (const float*)d_in[5];
    const float* se_b  = (const float*)d_in[6];
    const float* we_w  = (const float*)d_in[7];
    const float* emb   = (const float*)d_in[9];
    const float* w_ih  = (const float*)d_in[10];
    const float* w_hh  = (const float*)d_in[11];
    const float* b_ih  = (const float*)d_in[12];
    const float* b_hh  = (const float*)d_in[13];
    const float* fc_w  = (const float*)d_in[14];
    const float* fc_b  = (const float*)d_in[15];

    float* out = (float*)d_out;
    float* h_out = (out_size >= B_ * YD_ + B_ * 512) ? out + (size_t)B_ * YD_ : nullptr;

    float *sProj_p, *gi_p, *gh_p;
    cudaGetSymbolAddress((void**)&sProj_p, g_sProj);
    cudaGetSymbolAddress((void**)&gi_p, g_gi);
    cudaGetSymbolAddress((void**)&gh_p, g_gh);
    __nv_bfloat16 *x_t, *s_t, *cc_t, *h_t, *se_t, *hh_t, *ih_t, *fc_t;
    cudaGetSymbolAddress((void**)&x_t,  g_x_t);
    cudaGetSymbolAddress((void**)&s_t,  g_s_t);
    cudaGetSymbolAddress((void**)&cc_t, g_cc_t);
    cudaGetSymbolAddress((void**)&h_t,  g_h_t);
    cudaGetSymbolAddress((void**)&se_t, g_se_t);
    cudaGetSymbolAddress((void**)&hh_t, g_hh_t);
    cudaGetSymbolAddress((void**)&ih_t, g_ih_t);
    cudaGetSymbolAddress((void**)&fc_t, g_fc_t);

    static cudaStream_t s2 = nullptr;
    static cudaEvent_t evFork = nullptr, evW = nullptr, evX = nullptr, evGH = nullptr;
    if (!s2) {
        cudaFuncSetAttribute(bulk_scores,      cudaFuncAttributeMaxDynamicSharedMemorySize, SMEM_S);
        cudaFuncSetAttribute(bulk_gemm<false>, cudaFuncAttributeMaxDynamicSharedMemorySize, SMEM_G);
        cudaFuncSetAttribute(bulk_gemm<true>,  cudaFuncAttributeMaxDynamicSharedMemorySize, SMEM_G);
        cudaStreamCreateWithFlags(&s2, cudaStreamNonBlocking);
        cudaEventCreateWithFlags(&evFork, cudaEventDisableTiming);
        cudaEventCreateWithFlags(&evW, cudaEventDisableTiming);
        cudaEventCreateWithFlags(&evX, cudaEventDisableTiming);
        cudaEventCreateWithFlags(&evGH, cudaEventDisableTiming);
    }

    // ---- proper capture fork: s2 must first wait on an event recorded on
    //      the capture (default) stream before receiving any work ----
    cudaEventRecord(evFork, 0);
    cudaStreamWaitEvent(s2, evFork, 0);

    // ---- stream 2: x split (independent of weights) ----
    split_gen<<<16384, 256, 0, s2>>>(x, x_t, 65536, 512, 65536 * 64);
    cudaEventRecord(evX, s2);

    // ---- stream 1 (capture stream): s split, weight splits ----
    split_gen<<<64, 256>>>(sPrev, s_t, 256, 512, 256 * 64);
    split_weights<<<(784448 + 255) / 256, 256>>>(xe_w, se_w, w_hh, w_ih, fc_w);
    cudaEventRecord(evW, 0);

    // gh on s2 (needs weights + s split)
    cudaStreamWaitEvent(s2, evW, 0);
    bulk_gemm<false><<<dim3(6, 4), 256, SMEM_G, s2>>>(s_t, 256, hh_t, 1536, b_hh, gh_p, 1536, 512);
    cudaEventRecord(evGH, s2);

    // ---- main chain ----
    bulk_gemm<false><<<dim3(2, 4), 256, SMEM_G>>>(s_t, 256, se_t, 512, se_b, sProj_p, 512, 512);
    cudaStreamWaitEvent(0, evX, 0);
    bulk_scores<<<dim3(2, 512), 256, SMEM_S>>>(xe_b, we_w);
    softmax_ctx_cc<<<256, 256>>>(x, emb, yPrev);
    bulk_gemm<false><<<dim3(6, 4), 256, SMEM_G>>>(cc_t, 256, ih_t, 1536, b_ih, gi_p, 1536, 1024);
    cudaStreamWaitEvent(0, evGH, 0);
    gru_kernel<<<256, 256>>>(sPrev, h_out);
    bulk_gemm<true><<<dim3(26, 4), 256, SMEM_G>>>(h_t, 256, fc_t, 6656, fc_b, out, 6625, 512);
}